// round 7
// baseline (speedup 1.0000x reference)
#include <cuda_runtime.h>
#include <cuda_bf16.h>
#include <cstdint>
#include <math.h>

#define N_NODES 8192
#define DMODEL 1024
#define FINT 4096
#define KTOT 3072
#define NEDGE 262144
#define NKEY (2 * N_NODES)
#define LN_EPS 1e-6f

// ---------------- PTX helpers (sm_80-era: valid on base compute_103) ---------
__device__ __forceinline__ uint32_t smem_u32(const void* p) {
    uint32_t a;
    asm("{ .reg .u64 t; cvta.to.shared.u64 t, %1; cvt.u32.u64 %0, t; }" : "=r"(a) : "l"(p));
    return a;
}
#define CP16(dst, src) asm volatile("cp.async.cg.shared.global [%0], [%1], 16;" :: "r"(dst), "l"(src))
#define CP_COMMIT()    asm volatile("cp.async.commit_group;" ::: "memory")
#define CP_WAIT1()     asm volatile("cp.async.wait_group 1;" ::: "memory")

__device__ __forceinline__ void ldsm4(uint32_t* r, uint32_t a) {
    asm volatile("ldmatrix.sync.aligned.m8n8.x4.shared.b16 {%0,%1,%2,%3}, [%4];"
                 : "=r"(r[0]), "=r"(r[1]), "=r"(r[2]), "=r"(r[3]) : "r"(a));
}
__device__ __forceinline__ void ldsm4t(uint32_t* r, uint32_t a) {
    asm volatile("ldmatrix.sync.aligned.m8n8.x4.trans.shared.b16 {%0,%1,%2,%3}, [%4];"
                 : "=r"(r[0]), "=r"(r[1]), "=r"(r[2]), "=r"(r[3]) : "r"(a));
}
__device__ __forceinline__ void mma16816(float* d, const uint32_t* a, const uint32_t* b) {
    asm volatile("mma.sync.aligned.m16n8k16.row.col.f32.bf16.bf16.f32 "
                 "{%0,%1,%2,%3}, {%4,%5,%6,%7}, {%8,%9}, {%0,%1,%2,%3};"
                 : "+f"(d[0]), "+f"(d[1]), "+f"(d[2]), "+f"(d[3])
                 : "r"(a[0]), "r"(a[1]), "r"(a[2]), "r"(a[3]), "r"(b[0]), "r"(b[1]));
}

// ---------------- scratch ----------------------------------------------------
__device__ float g_x[(size_t)N_NODES * DMODEL];
__device__ __nv_bfloat16 g_Ahi[(size_t)N_NODES * KTOT];
__device__ __nv_bfloat16 g_Alo[(size_t)N_NODES * KTOT];
__device__ __nv_bfloat16 g_Bhi[(size_t)KTOT * FINT];
__device__ __nv_bfloat16 g_Blo[(size_t)KTOT * FINT];
__device__ __nv_bfloat16 g_Whi[(size_t)FINT * DMODEL];
__device__ __nv_bfloat16 g_Wlo[(size_t)FINT * DMODEL];
__device__ __nv_bfloat16 g_Mhi[(size_t)N_NODES * FINT];
__device__ __nv_bfloat16 g_Mlo[(size_t)N_NODES * FINT];
__device__ int g_cnt[NKEY];
__device__ int g_off[NKEY];
__device__ int g_cur[NKEY];
__device__ int g_srcbuf[NEDGE];

// ---------------- helpers ------------------------------------------------------
__device__ __forceinline__ void split2(float x0, float x1, ushort2& hv, ushort2& lv) {
    __nv_bfloat16 h0 = __float2bfloat16(x0);
    __nv_bfloat16 h1 = __float2bfloat16(x1);
    __nv_bfloat16 l0 = __float2bfloat16(x0 - __bfloat162float(h0));
    __nv_bfloat16 l1 = __float2bfloat16(x1 - __bfloat162float(h1));
    hv.x = *(unsigned short*)&h0; hv.y = *(unsigned short*)&h1;
    lv.x = *(unsigned short*)&l0; lv.y = *(unsigned short*)&l1;
}
__device__ __forceinline__ void split4(const float4& v, ushort4& hv, ushort4& lv) {
    ushort2 h01, l01, h23, l23;
    split2(v.x, v.y, h01, l01);
    split2(v.z, v.w, h23, l23);
    hv.x = h01.x; hv.y = h01.y; hv.z = h23.x; hv.w = h23.y;
    lv.x = l01.x; lv.y = l01.y; lv.z = l23.x; lv.w = l23.y;
}

// ---------------- pipeline kernels ---------------------------------------------
__global__ void zero_cnt_kernel() {
    int i = blockIdx.x * blockDim.x + threadIdx.x;
    if (i < NKEY) g_cnt[i] = 0;
}

__global__ __launch_bounds__(256) void ln_kernel(const float* __restrict__ hs,
                                                 const float* __restrict__ gamma,
                                                 const float* __restrict__ beta) {
    int n = blockIdx.x;
    int t = threadIdx.x;
    const float4 v = ((const float4*)(hs + (size_t)n * DMODEL))[t];
    float s  = v.x + v.y + v.z + v.w;
    float sq = v.x * v.x + v.y * v.y + v.z * v.z + v.w * v.w;
    __shared__ float red[16];
    for (int o = 16; o > 0; o >>= 1) {
        s  += __shfl_down_sync(0xffffffff, s,  o);
        sq += __shfl_down_sync(0xffffffff, sq, o);
    }
    int wid = t >> 5, lid = t & 31;
    if (lid == 0) { red[wid] = s; red[8 + wid] = sq; }
    __syncthreads();
    if (wid == 0) {
        s  = (lid < 8) ? red[lid]     : 0.f;
        sq = (lid < 8) ? red[8 + lid] : 0.f;
        for (int o = 4; o > 0; o >>= 1) {
            s  += __shfl_down_sync(0xffffffff, s,  o);
            sq += __shfl_down_sync(0xffffffff, sq, o);
        }
        if (lid == 0) { red[0] = s; red[1] = sq; }
    }
    __syncthreads();
    float mean = red[0] * (1.f / DMODEL);
    float var  = red[1] * (1.f / DMODEL) - mean * mean;
    float rstd = rsqrtf(var + LN_EPS);
    const float4 g = ((const float4*)gamma)[t];
    const float4 b = ((const float4*)beta)[t];
    float4 o;
    o.x = (v.x - mean) * rstd * g.x + b.x;
    o.y = (v.y - mean) * rstd * g.y + b.y;
    o.z = (v.z - mean) * rstd * g.z + b.z;
    o.w = (v.w - mean) * rstd * g.w + b.w;
    *(float4*)&g_x[(size_t)n * DMODEL + t * 4] = o;
    ushort4 hv, lv;
    split4(o, hv, lv);
    size_t a = ((size_t)n * KTOT + 2048) / 4 + t;
    ((ushort4*)g_Ahi)[a] = hv;
    ((ushort4*)g_Alo)[a] = lv;
}

__global__ void count_kernel(const int* __restrict__ ei, const int* __restrict__ et) {
    int e = blockIdx.x * blockDim.x + threadIdx.x;
    if (e < NEDGE) atomicAdd(&g_cnt[et[e] * N_NODES + ei[NEDGE + e]], 1);
}

// two-level shfl scan over 16384 counts (1024 threads x 16)
__global__ __launch_bounds__(1024) void scan_kernel() {
    int tid = threadIdx.x;
    int lane = tid & 31, wid = tid >> 5;
    int base = tid * 16;
    int loc[16];
    int s = 0;
    #pragma unroll
    for (int i = 0; i < 16; i++) { loc[i] = s; s += g_cnt[base + i]; }
    int inc = s;
    #pragma unroll
    for (int o = 1; o < 32; o <<= 1) {
        int v = __shfl_up_sync(0xffffffff, inc, o);
        if (lane >= o) inc += v;
    }
    __shared__ int wtot[32];
    if (lane == 31) wtot[wid] = inc;
    __syncthreads();
    if (wid == 0) {
        int w = wtot[lane];
        int wi = w;
        #pragma unroll
        for (int o = 1; o < 32; o <<= 1) {
            int v = __shfl_up_sync(0xffffffff, wi, o);
            if (lane >= o) wi += v;
        }
        wtot[lane] = wi - w;
    }
    __syncthreads();
    int ex = wtot[wid] + (inc - s);
    #pragma unroll
    for (int i = 0; i < 16; i++) {
        int o = ex + loc[i];
        g_off[base + i] = o;
        g_cur[base + i] = o;
    }
}

__global__ void bucket_kernel(const int* __restrict__ ei, const int* __restrict__ et) {
    int e = blockIdx.x * blockDim.x + threadIdx.x;
    if (e < NEDGE) {
        int key = et[e] * N_NODES + ei[NEDGE + e];
        int pos = atomicAdd(&g_cur[key], 1);
        g_srcbuf[pos] = ei[e];
    }
}

__global__ __launch_bounds__(256) void gather_kernel() {
    int key = blockIdx.x;
    int node = key & (N_NODES - 1);
    int r = key >> 13;
    int off = g_off[key];
    int cnt = g_cnt[key];
    int c = threadIdx.x * 4;

    float4 acc = make_float4(0.f, 0.f, 0.f, 0.f);
    int i = 0;
    for (; i + 4 <= cnt; i += 4) {
        int s0 = g_srcbuf[off + i];
        int s1 = g_srcbuf[off + i + 1];
        int s2 = g_srcbuf[off + i + 2];
        int s3 = g_srcbuf[off + i + 3];
        float4 v0 = *(const float4*)&g_x[(size_t)s0 * DMODEL + c];
        float4 v1 = *(const float4*)&g_x[(size_t)s1 * DMODEL + c];
        float4 v2 = *(const float4*)&g_x[(size_t)s2 * DMODEL + c];
        float4 v3 = *(const float4*)&g_x[(size_t)s3 * DMODEL + c];
        acc.x += (v0.x + v1.x) + (v2.x + v3.x);
        acc.y += (v0.y + v1.y) + (v2.y + v3.y);
        acc.z += (v0.z + v1.z) + (v2.z + v3.z);
        acc.w += (v0.w + v1.w) + (v2.w + v3.w);
    }
    for (; i < cnt; i++) {
        int s0 = g_srcbuf[off + i];
        float4 v0 = *(const float4*)&g_x[(size_t)s0 * DMODEL + c];
        acc.x += v0.x; acc.y += v0.y; acc.z += v0.z; acc.w += v0.w;
    }
    float sc = 1.f / (float)max(cnt, 1);
    acc.x *= sc; acc.y *= sc; acc.z *= sc; acc.w *= sc;
    ushort4 hv, lv;
    split4(acc, hv, lv);
    size_t a = ((size_t)node * KTOT + (size_t)r * 1024 + c) >> 2;
    ((ushort4*)g_Ahi)[a] = hv;
    ((ushort4*)g_Alo)[a] = lv;
}

__global__ void split_kernel(const float* __restrict__ src,
                             __nv_bfloat16* __restrict__ hi,
                             __nv_bfloat16* __restrict__ lo, size_t n4) {
    size_t i = (size_t)blockIdx.x * blockDim.x + threadIdx.x;
    for (; i < n4; i += (size_t)gridDim.x * blockDim.x) {
        float4 v = ((const float4*)src)[i];
        ushort4 hv, lv;
        split4(v, hv, lv);
        ((ushort4*)hi)[i] = hv;
        ((ushort4*)lo)[i] = lv;
    }
}

// ---------------- mma.sync split-bf16 GEMM, CTA 128x256, warp 64x64 ------------
#define STAGE_BYTES 98304
#define OFF_ALO 16384
#define OFF_BHI 32768
#define OFF_BLO 65536
#define SMEM_DYN (2 * STAGE_BYTES)
#define EPIPITCH 264

__device__ __forceinline__ uint32_t a_off(int row, int q) {
    return (uint32_t)(row * 128 + ((q ^ (row & 7)) << 4));
}
__device__ __forceinline__ uint32_t b_off(int row, int q) {
    return (uint32_t)(row * 512 + (((q & 24) | ((q & 7) ^ (row & 7))) << 4));
}

__global__ __launch_bounds__(256, 1) void gemm_mma(
    const __nv_bfloat16* __restrict__ Ahi, const __nv_bfloat16* __restrict__ Alo,
    int ldA, int K,
    const __nv_bfloat16* __restrict__ Bhi, const __nv_bfloat16* __restrict__ Blo,
    int ldB,
    const float* __restrict__ bias, const float* __restrict__ residual,
    float* __restrict__ outF,
    __nv_bfloat16* __restrict__ outHi, __nv_bfloat16* __restrict__ outLo,
    int mode, int mOff)
{
    extern __shared__ __align__(1024) char smem[];
    const uint32_t sb = smem_u32(smem);
    const int tid = threadIdx.x, wid = tid >> 5, lane = tid & 31;
    const int rowBase = (blockIdx.y + mOff) * 128;
    const int nBase   = blockIdx.x * 256;
    const int warp_m = (wid >> 2) * 64;
    const int warp_n = (wid & 3) * 64;
    const int lr = lane & 15, lc = lane >> 4;
    const int nchunk = K >> 6;

    float acc[4][8][4];
    #pragma unroll
    for (int i = 0; i < 4; i++)
        #pragma unroll
        for (int j = 0; j < 8; j++)
            #pragma unroll
            for (int k = 0; k < 4; k++) acc[i][j][k] = 0.f;

    auto load_chunk = [&](int c, int s) {
        const uint32_t sbase = sb + s * STAGE_BYTES;
        const int kb = c * 64;
        #pragma unroll
        for (int i = 0; i < 4; i++) {
            int v = tid + i * 256;
            int row = v >> 3, q = v & 7;
            uint32_t so = sbase + a_off(row, q);
            size_t g = (size_t)(rowBase + row) * ldA + kb + q * 8;
            CP16(so, Ahi + g);
            CP16(so + OFF_ALO, Alo + g);
        }
        #pragma unroll
        for (int i = 0; i < 8; i++) {
            int v = tid + i * 256;
            int row = v >> 5, q = v & 31;
            uint32_t so = sbase + OFF_BHI + b_off(row, q);
            size_t g = (size_t)(kb + row) * ldB + nBase + q * 8;
            CP16(so, Bhi + g);
            CP16(so + (OFF_BLO - OFF_BHI), Blo + g);
        }
    };

    load_chunk(0, 0); CP_COMMIT();
    load_chunk(1, 1); CP_COMMIT();

    for (int c = 0; c < nchunk; c++) {
        CP_WAIT1();
        __syncthreads();
        const uint32_t base = sb + (c & 1) * STAGE_BYTES;
        #pragma unroll
        for (int ks = 0; ks < 4; ks++) {
            uint32_t ah[4][4], al[4][4];
            #pragma unroll
            for (int mi = 0; mi < 4; mi++) {
                int row = warp_m + mi * 16 + lr;
                int q = ks * 2 + lc;
                uint32_t addr = base + a_off(row, q);
                ldsm4(ah[mi], addr);
                ldsm4(al[mi], addr + OFF_ALO);
            }
            #pragma unroll
            for (int np = 0; np < 4; np++) {
                int row = ks * 16 + lr;
                int q = (warp_n >> 3) + np * 2 + lc;
                uint32_t addr = base + OFF_BHI + b_off(row, q);
                uint32_t th[4], tl[4];
                ldsm4t(th, addr);
                ldsm4t(tl, addr + (OFF_BLO - OFF_BHI));
                uint32_t bh0[2] = { th[0], th[1] }, bh1[2] = { th[2], th[3] };
                uint32_t bl0[2] = { tl[0], tl[1] }, bl1[2] = { tl[2], tl[3] };
                #pragma unroll
                for (int mi = 0; mi < 4; mi++) {
                    mma16816(acc[mi][np * 2], ah[mi], bh0);
                    mma16816(acc[mi][np * 2], ah[mi], bl0);
                    mma16816(acc[mi][np * 2], al[mi], bh0);
                    mma16816(acc[mi][np * 2 + 1], ah[mi], bh1);
                    mma16816(acc[mi][np * 2 + 1], ah[mi], bl1);
                    mma16816(acc[mi][np * 2 + 1], al[mi], bh1);
                }
            }
        }
        __syncthreads();
        if (c + 2 < nchunk) load_chunk(c + 2, c & 1);
        CP_COMMIT();
    }

    if (mode == 1) {
        unsigned short* stH = (unsigned short*)smem;
        unsigned short* stL = stH + 128 * EPIPITCH;
        #pragma unroll
        for (int mi = 0; mi < 4; mi++) {
            #pragma unroll
            for (int ni = 0; ni < 8; ni++) {
                int rl0 = warp_m + mi * 16 + (lane >> 2);
                int cl  = warp_n + ni * 8 + (lane & 3) * 2;
                #pragma unroll
                for (int h = 0; h < 2; h++) {
                    int rl = rl0 + h * 8;
                    float x0 = acc[mi][ni][h * 2 + 0];
                    float x1 = acc[mi][ni][h * 2 + 1];
                    int gc = nBase + cl;
                    x0 = fmaxf(x0 + bias[gc], 0.f);
                    x1 = fmaxf(x1 + bias[gc + 1], 0.f);
                    ushort2 hv, lv;
                    split2(x0, x1, hv, lv);
                    *(ushort2*)&stH[rl * EPIPITCH + cl] = hv;
                    *(ushort2*)&stL[rl * EPIPITCH + cl] = lv;
                }
            }
        }
        __syncthreads();
        #pragma unroll
        for (int i = 0; i < 16; i++) {
            int idx = tid + i * 256;
            int row = idx >> 5, ch = idx & 31;
            uint4 vh = *(uint4*)&stH[row * EPIPITCH + ch * 8];
            uint4 vl = *(uint4*)&stL[row * EPIPITCH + ch * 8];
            size_t go = (size_t)(rowBase + row) * ldB + nBase + ch * 8;
            *(uint4*)&outHi[go] = vh;
            *(uint4*)&outLo[go] = vl;
        }
    } else {
        #pragma unroll
        for (int mi = 0; mi < 4; mi++) {
            #pragma unroll
            for (int ni = 0; ni < 8; ni++) {
                int r0 = rowBase + warp_m + mi * 16 + (lane >> 2);
                int col = nBase + warp_n + ni * 8 + (lane & 3) * 2;
                #pragma unroll
                for (int h = 0; h < 2; h++) {
                    int row = r0 + h * 8;
                    float x0 = acc[mi][ni][h * 2 + 0];
                    float x1 = acc[mi][ni][h * 2 + 1];
                    size_t go = (size_t)row * ldB + col;
                    float2 res = *(const float2*)&residual[go];
                    float2 y = { x0 + res.x, x1 + res.y };
                    *(float2*)&outF[go] = y;
                }
            }
        }
    }
}

// ---------------- launch -------------------------------------------------------
extern "C" void kernel_launch(void* const* d_in, const int* in_sizes, int n_in,
                              void* d_out, int out_size) {
    const float* hidden = (const float*)d_in[0];
    const float* weight = (const float*)d_in[1];
    const float* root   = (const float*)d_in[2];
    const float* bias   = (const float*)d_in[3];
    const float* wo     = (const float*)d_in[4];
    const float* gamma  = (const float*)d_in[5];
    const float* beta   = (const float*)d_in[6];
    const int*   ei     = (const int*)d_in[7];
    const int*   et     = (const int*)d_in[8];
    float* out = (float*)d_out;

    __nv_bfloat16 *gAhi, *gAlo, *gBhi, *gBlo, *gWhi, *gWlo, *gMhi, *gMlo;
    cudaGetSymbolAddress((void**)&gAhi, g_Ahi);
    cudaGetSymbolAddress((void**)&gAlo, g_Alo);
    cudaGetSymbolAddress((void**)&gBhi, g_Bhi);
    cudaGetSymbolAddress((void**)&gBlo, g_Blo);
    cudaGetSymbolAddress((void**)&gWhi, g_Whi);
    cudaGetSymbolAddress((void**)&gWlo, g_Wlo);
    cudaGetSymbolAddress((void**)&gMhi, g_Mhi);
    cudaGetSymbolAddress((void**)&gMlo, g_Mlo);

    cudaFuncSetAttribute(gemm_mma, cudaFuncAttributeMaxDynamicSharedMemorySize, SMEM_DYN);

    // lazily-created host-side handles (no device memory involved)
    static cudaStream_t sA = nullptr;
    static cudaEvent_t evFork = nullptr, evA = nullptr, evG1a = nullptr, evG2a = nullptr;
    if (!sA) {
        cudaStreamCreateWithFlags(&sA, cudaStreamNonBlocking);
        cudaEventCreateWithFlags(&evFork, cudaEventDisableTiming);
        cudaEventCreateWithFlags(&evA,    cudaEventDisableTiming);
        cudaEventCreateWithFlags(&evG1a,  cudaEventDisableTiming);
        cudaEventCreateWithFlags(&evG2a,  cudaEventDisableTiming);
    }

    // fork: side stream sA handles the edge-index chain
    cudaEventRecord(evFork, 0);
    cudaStreamWaitEvent(sA, evFork, 0);

    // stream A: zero -> count -> scan -> bucket
    zero_cnt_kernel<<<NKEY / 256, 256, 0, sA>>>();
    count_kernel<<<NEDGE / 256, 256, 0, sA>>>(ei, et);
    scan_kernel<<<1, 1024, 0, sA>>>();
    bucket_kernel<<<NEDGE / 256, 256, 0, sA>>>(ei, et);
    cudaEventRecord(evA, sA);

    // stream 0 (capture stream): ln + weight splits (independent of edge chain)
    ln_kernel<<<N_NODES, 256>>>(hidden, gamma, beta);
    split_kernel<<<2048, 256>>>(weight, gBhi, gBlo, (size_t)2048 * FINT / 4);
    split_kernel<<<1024, 256>>>(root, gBhi + (size_t)2048 * FINT, gBlo + (size_t)2048 * FINT,
                                (size_t)1024 * FINT / 4);
    split_kernel<<<1024, 256>>>(wo, gWhi, gWlo, (size_t)FINT * DMODEL / 4);

    // join: gather needs bucket (sA) + ln (s0)
    cudaStreamWaitEvent(0, evA, 0);
    gather_kernel<<<NKEY, 256>>>();

    // GEMM1 in two M-halves on s0; GEMM2 first half overlaps GEMM1 second half on sA
    gemm_mma<<<dim3(FINT / 256, 32), 256, SMEM_DYN>>>(
        gAhi, gAlo, KTOT, KTOT, gBhi, gBlo, FINT,
        bias, nullptr, nullptr, gMhi, gMlo, 1, 0);
    cudaEventRecord(evG1a, 0);

    gemm_mma<<<dim3(FINT / 256, 32), 256, SMEM_DYN>>>(
        gAhi, gAlo, KTOT, KTOT, gBhi, gBlo, FINT,
        bias, nullptr, nullptr, gMhi, gMlo, 1, 32);

    cudaStreamWaitEvent(sA, evG1a, 0);
    gemm_mma<<<dim3(DMODEL / 256, 32), 256, SMEM_DYN, sA>>>(
        gMhi, gMlo, FINT, FINT, gWhi, gWlo, DMODEL,
        nullptr, hidden, out, nullptr, nullptr, 2, 0);
    cudaEventRecord(evG2a, sA);

    gemm_mma<<<dim3(DMODEL / 256, 32), 256, SMEM_DYN>>>(
        gMhi, gMlo, FINT, FINT, gWhi, gWlo, DMODEL,
        nullptr, hidden, out, nullptr, nullptr, 2, 32);

    // join side stream back into the capture stream
    cudaStreamWaitEvent(0, evG2a, 0);
}

// round 8
// speedup vs baseline: 1.0974x; 1.0974x over previous
#include <cuda_runtime.h>
#include <cuda_bf16.h>
#include <cstdint>
#include <math.h>

#define N_NODES 8192
#define DMODEL 1024
#define FINT 4096
#define KTOT 3072
#define NEDGE 262144
#define NKEY (2 * N_NODES)
#define LN_EPS 1e-6f

// ---------------- PTX helpers (sm_80-era: valid on base compute_103) ---------
__device__ __forceinline__ uint32_t smem_u32(const void* p) {
    uint32_t a;
    asm("{ .reg .u64 t; cvta.to.shared.u64 t, %1; cvt.u32.u64 %0, t; }" : "=r"(a) : "l"(p));
    return a;
}
#define CP16(dst, src) asm volatile("cp.async.cg.shared.global [%0], [%1], 16;" :: "r"(dst), "l"(src))
#define CP_COMMIT()    asm volatile("cp.async.commit_group;" ::: "memory")
#define CP_WAIT1()     asm volatile("cp.async.wait_group 1;" ::: "memory")

__device__ __forceinline__ void ldsm4(uint32_t* r, uint32_t a) {
    asm volatile("ldmatrix.sync.aligned.m8n8.x4.shared.b16 {%0,%1,%2,%3}, [%4];"
                 : "=r"(r[0]), "=r"(r[1]), "=r"(r[2]), "=r"(r[3]) : "r"(a));
}
__device__ __forceinline__ void ldsm4t(uint32_t* r, uint32_t a) {
    asm volatile("ldmatrix.sync.aligned.m8n8.x4.trans.shared.b16 {%0,%1,%2,%3}, [%4];"
                 : "=r"(r[0]), "=r"(r[1]), "=r"(r[2]), "=r"(r[3]) : "r"(a));
}
__device__ __forceinline__ void mma16816(float* d, const uint32_t* a, const uint32_t* b) {
    asm volatile("mma.sync.aligned.m16n8k16.row.col.f32.bf16.bf16.f32 "
                 "{%0,%1,%2,%3}, {%4,%5,%6,%7}, {%8,%9}, {%0,%1,%2,%3};"
                 : "+f"(d[0]), "+f"(d[1]), "+f"(d[2]), "+f"(d[3])
                 : "r"(a[0]), "r"(a[1]), "r"(a[2]), "r"(a[3]), "r"(b[0]), "r"(b[1]));
}

// ---------------- scratch ----------------------------------------------------
__device__ float g_x[(size_t)N_NODES * DMODEL];
__device__ __nv_bfloat16 g_Ahi[(size_t)N_NODES * KTOT];
__device__ __nv_bfloat16 g_Alo[(size_t)N_NODES * KTOT];
__device__ __nv_bfloat16 g_Bhi[(size_t)KTOT * FINT];
__device__ __nv_bfloat16 g_Blo[(size_t)KTOT * FINT];
__device__ __nv_bfloat16 g_Whi[(size_t)FINT * DMODEL];
__device__ __nv_bfloat16 g_Wlo[(size_t)FINT * DMODEL];
__device__ __nv_bfloat16 g_Mhi[(size_t)N_NODES * FINT];
__device__ __nv_bfloat16 g_Mlo[(size_t)N_NODES * FINT];
__device__ int g_cnt[NKEY];
__device__ int g_off[NKEY];
__device__ int g_cur[NKEY];
__device__ int g_srcbuf[NEDGE];

// ---------------- helpers ------------------------------------------------------
__device__ __forceinline__ void split2(float x0, float x1, ushort2& hv, ushort2& lv) {
    __nv_bfloat16 h0 = __float2bfloat16(x0);
    __nv_bfloat16 h1 = __float2bfloat16(x1);
    __nv_bfloat16 l0 = __float2bfloat16(x0 - __bfloat162float(h0));
    __nv_bfloat16 l1 = __float2bfloat16(x1 - __bfloat162float(h1));
    hv.x = *(unsigned short*)&h0; hv.y = *(unsigned short*)&h1;
    lv.x = *(unsigned short*)&l0; lv.y = *(unsigned short*)&l1;
}
__device__ __forceinline__ void split4(const float4& v, ushort4& hv, ushort4& lv) {
    ushort2 h01, l01, h23, l23;
    split2(v.x, v.y, h01, l01);
    split2(v.z, v.w, h23, l23);
    hv.x = h01.x; hv.y = h01.y; hv.z = h23.x; hv.w = h23.y;
    lv.x = l01.x; lv.y = l01.y; lv.z = l23.x; lv.w = l23.y;
}

// ---------------- pipeline kernels ---------------------------------------------
__global__ void zero_cnt_kernel() {
    int i = blockIdx.x * blockDim.x + threadIdx.x;
    if (i < NKEY) g_cnt[i] = 0;
}

__global__ __launch_bounds__(256) void ln_kernel(const float* __restrict__ hs,
                                                 const float* __restrict__ gamma,
                                                 const float* __restrict__ beta) {
    int n = blockIdx.x;
    int t = threadIdx.x;
    const float4 v = ((const float4*)(hs + (size_t)n * DMODEL))[t];
    float s  = v.x + v.y + v.z + v.w;
    float sq = v.x * v.x + v.y * v.y + v.z * v.z + v.w * v.w;
    __shared__ float red[16];
    for (int o = 16; o > 0; o >>= 1) {
        s  += __shfl_down_sync(0xffffffff, s,  o);
        sq += __shfl_down_sync(0xffffffff, sq, o);
    }
    int wid = t >> 5, lid = t & 31;
    if (lid == 0) { red[wid] = s; red[8 + wid] = sq; }
    __syncthreads();
    if (wid == 0) {
        s  = (lid < 8) ? red[lid]     : 0.f;
        sq = (lid < 8) ? red[8 + lid] : 0.f;
        for (int o = 4; o > 0; o >>= 1) {
            s  += __shfl_down_sync(0xffffffff, s,  o);
            sq += __shfl_down_sync(0xffffffff, sq, o);
        }
        if (lid == 0) { red[0] = s; red[1] = sq; }
    }
    __syncthreads();
    float mean = red[0] * (1.f / DMODEL);
    float var  = red[1] * (1.f / DMODEL) - mean * mean;
    float rstd = rsqrtf(var + LN_EPS);
    const float4 g = ((const float4*)gamma)[t];
    const float4 b = ((const float4*)beta)[t];
    float4 o;
    o.x = (v.x - mean) * rstd * g.x + b.x;
    o.y = (v.y - mean) * rstd * g.y + b.y;
    o.z = (v.z - mean) * rstd * g.z + b.z;
    o.w = (v.w - mean) * rstd * g.w + b.w;
    *(float4*)&g_x[(size_t)n * DMODEL + t * 4] = o;
    ushort4 hv, lv;
    split4(o, hv, lv);
    size_t a = ((size_t)n * KTOT + 2048) / 4 + t;
    ((ushort4*)g_Ahi)[a] = hv;
    ((ushort4*)g_Alo)[a] = lv;
}

__global__ void count_kernel(const int* __restrict__ ei, const int* __restrict__ et) {
    int e = blockIdx.x * blockDim.x + threadIdx.x;
    if (e < NEDGE) atomicAdd(&g_cnt[et[e] * N_NODES + ei[NEDGE + e]], 1);
}

// two-level shfl scan over 16384 counts (1024 threads x 16)
__global__ __launch_bounds__(1024) void scan_kernel() {
    int tid = threadIdx.x;
    int lane = tid & 31, wid = tid >> 5;
    int base = tid * 16;
    int loc[16];
    int s = 0;
    #pragma unroll
    for (int i = 0; i < 16; i++) { loc[i] = s; s += g_cnt[base + i]; }
    int inc = s;
    #pragma unroll
    for (int o = 1; o < 32; o <<= 1) {
        int v = __shfl_up_sync(0xffffffff, inc, o);
        if (lane >= o) inc += v;
    }
    __shared__ int wtot[32];
    if (lane == 31) wtot[wid] = inc;
    __syncthreads();
    if (wid == 0) {
        int w = wtot[lane];
        int wi = w;
        #pragma unroll
        for (int o = 1; o < 32; o <<= 1) {
            int v = __shfl_up_sync(0xffffffff, wi, o);
            if (lane >= o) wi += v;
        }
        wtot[lane] = wi - w;
    }
    __syncthreads();
    int ex = wtot[wid] + (inc - s);
    #pragma unroll
    for (int i = 0; i < 16; i++) {
        int o = ex + loc[i];
        g_off[base + i] = o;
        g_cur[base + i] = o;
    }
}

__global__ void bucket_kernel(const int* __restrict__ ei, const int* __restrict__ et) {
    int e = blockIdx.x * blockDim.x + threadIdx.x;
    if (e < NEDGE) {
        int key = et[e] * N_NODES + ei[NEDGE + e];
        int pos = atomicAdd(&g_cur[key], 1);
        g_srcbuf[pos] = ei[e];
    }
}

__global__ __launch_bounds__(256) void gather_kernel() {
    int key = blockIdx.x;
    int node = key & (N_NODES - 1);
    int r = key >> 13;
    int off = g_off[key];
    int cnt = g_cnt[key];
    int c = threadIdx.x * 4;

    float4 acc = make_float4(0.f, 0.f, 0.f, 0.f);
    int i = 0;
    for (; i + 4 <= cnt; i += 4) {
        int s0 = g_srcbuf[off + i];
        int s1 = g_srcbuf[off + i + 1];
        int s2 = g_srcbuf[off + i + 2];
        int s3 = g_srcbuf[off + i + 3];
        float4 v0 = *(const float4*)&g_x[(size_t)s0 * DMODEL + c];
        float4 v1 = *(const float4*)&g_x[(size_t)s1 * DMODEL + c];
        float4 v2 = *(const float4*)&g_x[(size_t)s2 * DMODEL + c];
        float4 v3 = *(const float4*)&g_x[(size_t)s3 * DMODEL + c];
        acc.x += (v0.x + v1.x) + (v2.x + v3.x);
        acc.y += (v0.y + v1.y) + (v2.y + v3.y);
        acc.z += (v0.z + v1.z) + (v2.z + v3.z);
        acc.w += (v0.w + v1.w) + (v2.w + v3.w);
    }
    for (; i < cnt; i++) {
        int s0 = g_srcbuf[off + i];
        float4 v0 = *(const float4*)&g_x[(size_t)s0 * DMODEL + c];
        acc.x += v0.x; acc.y += v0.y; acc.z += v0.z; acc.w += v0.w;
    }
    float sc = 1.f / (float)max(cnt, 1);
    acc.x *= sc; acc.y *= sc; acc.z *= sc; acc.w *= sc;
    ushort4 hv, lv;
    split4(acc, hv, lv);
    size_t a = ((size_t)node * KTOT + (size_t)r * 1024 + c) >> 2;
    ((ushort4*)g_Ahi)[a] = hv;
    ((ushort4*)g_Alo)[a] = lv;
}

__global__ void split_kernel(const float* __restrict__ src,
                             __nv_bfloat16* __restrict__ hi,
                             __nv_bfloat16* __restrict__ lo, size_t n4) {
    size_t i = (size_t)blockIdx.x * blockDim.x + threadIdx.x;
    for (; i < n4; i += (size_t)gridDim.x * blockDim.x) {
        float4 v = ((const float4*)src)[i];
        ushort4 hv, lv;
        split4(v, hv, lv);
        ((ushort4*)hi)[i] = hv;
        ((ushort4*)lo)[i] = lv;
    }
}

// ---------------- mma.sync split-bf16 GEMM, CTA 128x256, warp 64x64 ------------
#define STAGE_BYTES 98304
#define OFF_ALO 16384
#define OFF_BHI 32768
#define OFF_BLO 65536
#define SMEM_DYN (2 * STAGE_BYTES)
#define EPIPITCH 264

__device__ __forceinline__ uint32_t a_off(int row, int q) {
    return (uint32_t)(row * 128 + ((q ^ (row & 7)) << 4));
}
__device__ __forceinline__ uint32_t b_off(int row, int q) {
    return (uint32_t)(row * 512 + (((q & 24) | ((q & 7) ^ (row & 7))) << 4));
}

__global__ __launch_bounds__(256, 1) void gemm_mma(
    const __nv_bfloat16* __restrict__ Ahi, const __nv_bfloat16* __restrict__ Alo,
    int ldA, int K,
    const __nv_bfloat16* __restrict__ Bhi, const __nv_bfloat16* __restrict__ Blo,
    int ldB,
    const float* __restrict__ bias, const float* __restrict__ residual,
    float* __restrict__ outF,
    __nv_bfloat16* __restrict__ outHi, __nv_bfloat16* __restrict__ outLo,
    int mode)
{
    extern __shared__ __align__(1024) char smem[];
    const uint32_t sb = smem_u32(smem);
    const int tid = threadIdx.x, wid = tid >> 5, lane = tid & 31;
    const int rowBase = blockIdx.y * 128;
    const int nBase   = blockIdx.x * 256;
    const int warp_m = (wid >> 2) * 64;
    const int warp_n = (wid & 3) * 64;
    const int lr = lane & 15, lc = lane >> 4;
    const int nchunk = K >> 6;

    float acc[4][8][4];
    #pragma unroll
    for (int i = 0; i < 4; i++)
        #pragma unroll
        for (int j = 0; j < 8; j++)
            #pragma unroll
            for (int k = 0; k < 4; k++) acc[i][j][k] = 0.f;

    auto load_chunk = [&](int c, int s) {
        const uint32_t sbase = sb + s * STAGE_BYTES;
        const int kb = c * 64;
        #pragma unroll
        for (int i = 0; i < 4; i++) {
            int v = tid + i * 256;
            int row = v >> 3, q = v & 7;
            uint32_t so = sbase + a_off(row, q);
            size_t g = (size_t)(rowBase + row) * ldA + kb + q * 8;
            CP16(so, Ahi + g);
            CP16(so + OFF_ALO, Alo + g);
        }
        #pragma unroll
        for (int i = 0; i < 8; i++) {
            int v = tid + i * 256;
            int row = v >> 5, q = v & 31;
            uint32_t so = sbase + OFF_BHI + b_off(row, q);
            size_t g = (size_t)(kb + row) * ldB + nBase + q * 8;
            CP16(so, Bhi + g);
            CP16(so + (OFF_BLO - OFF_BHI), Blo + g);
        }
    };

    load_chunk(0, 0); CP_COMMIT();
    load_chunk(1, 1); CP_COMMIT();

    for (int c = 0; c < nchunk; c++) {
        CP_WAIT1();
        __syncthreads();
        const uint32_t base = sb + (c & 1) * STAGE_BYTES;
        #pragma unroll
        for (int ks = 0; ks < 4; ks++) {
            uint32_t ah[4][4], al[4][4];
            #pragma unroll
            for (int mi = 0; mi < 4; mi++) {
                int row = warp_m + mi * 16 + lr;
                int q = ks * 2 + lc;
                uint32_t addr = base + a_off(row, q);
                ldsm4(ah[mi], addr);
                ldsm4(al[mi], addr + OFF_ALO);
            }
            #pragma unroll
            for (int np = 0; np < 4; np++) {
                int row = ks * 16 + lr;
                int q = (warp_n >> 3) + np * 2 + lc;
                uint32_t addr = base + OFF_BHI + b_off(row, q);
                uint32_t th[4], tl[4];
                ldsm4t(th, addr);
                ldsm4t(tl, addr + (OFF_BLO - OFF_BHI));
                uint32_t bh0[2] = { th[0], th[1] }, bh1[2] = { th[2], th[3] };
                uint32_t bl0[2] = { tl[0], tl[1] }, bl1[2] = { tl[2], tl[3] };
                #pragma unroll
                for (int mi = 0; mi < 4; mi++) {
                    mma16816(acc[mi][np * 2], ah[mi], bh0);
                    mma16816(acc[mi][np * 2], ah[mi], bl0);
                    mma16816(acc[mi][np * 2], al[mi], bh0);
                    mma16816(acc[mi][np * 2 + 1], ah[mi], bh1);
                    mma16816(acc[mi][np * 2 + 1], ah[mi], bl1);
                    mma16816(acc[mi][np * 2 + 1], al[mi], bh1);
                }
            }
        }
        __syncthreads();
        if (c + 2 < nchunk) load_chunk(c + 2, c & 1);
        CP_COMMIT();
    }

    if (mode == 1) {
        unsigned short* stH = (unsigned short*)smem;
        unsigned short* stL = stH + 128 * EPIPITCH;
        #pragma unroll
        for (int mi = 0; mi < 4; mi++) {
            #pragma unroll
            for (int ni = 0; ni < 8; ni++) {
                int rl0 = warp_m + mi * 16 + (lane >> 2);
                int cl  = warp_n + ni * 8 + (lane & 3) * 2;
                #pragma unroll
                for (int h = 0; h < 2; h++) {
                    int rl = rl0 + h * 8;
                    float x0 = acc[mi][ni][h * 2 + 0];
                    float x1 = acc[mi][ni][h * 2 + 1];
                    int gc = nBase + cl;
                    x0 = fmaxf(x0 + bias[gc], 0.f);
                    x1 = fmaxf(x1 + bias[gc + 1], 0.f);
                    ushort2 hv, lv;
                    split2(x0, x1, hv, lv);
                    *(ushort2*)&stH[rl * EPIPITCH + cl] = hv;
                    *(ushort2*)&stL[rl * EPIPITCH + cl] = lv;
                }
            }
        }
        __syncthreads();
        #pragma unroll
        for (int i = 0; i < 16; i++) {
            int idx = tid + i * 256;
            int row = idx >> 5, ch = idx & 31;
            uint4 vh = *(uint4*)&stH[row * EPIPITCH + ch * 8];
            uint4 vl = *(uint4*)&stL[row * EPIPITCH + ch * 8];
            size_t go = (size_t)(rowBase + row) * ldB + nBase + ch * 8;
            *(uint4*)&outHi[go] = vh;
            *(uint4*)&outLo[go] = vl;
        }
    } else {
        #pragma unroll
        for (int mi = 0; mi < 4; mi++) {
            #pragma unroll
            for (int ni = 0; ni < 8; ni++) {
                int r0 = rowBase + warp_m + mi * 16 + (lane >> 2);
                int col = nBase + warp_n + ni * 8 + (lane & 3) * 2;
                #pragma unroll
                for (int h = 0; h < 2; h++) {
                    int row = r0 + h * 8;
                    float x0 = acc[mi][ni][h * 2 + 0];
                    float x1 = acc[mi][ni][h * 2 + 1];
                    size_t go = (size_t)row * ldB + col;
                    float2 res = *(const float2*)&residual[go];
                    float2 y = { x0 + res.x, x1 + res.y };
                    *(float2*)&outF[go] = y;
                }
            }
        }
    }
}

// ---------------- launch -------------------------------------------------------
extern "C" void kernel_launch(void* const* d_in, const int* in_sizes, int n_in,
                              void* d_out, int out_size) {
    const float* hidden = (const float*)d_in[0];
    const float* weight = (const float*)d_in[1];
    const float* root   = (const float*)d_in[2];
    const float* bias   = (const float*)d_in[3];
    const float* wo     = (const float*)d_in[4];
    const float* gamma  = (const float*)d_in[5];
    const float* beta   = (const float*)d_in[6];
    const int*   ei     = (const int*)d_in[7];
    const int*   et     = (const int*)d_in[8];
    float* out = (float*)d_out;

    __nv_bfloat16 *gAhi, *gAlo, *gBhi, *gBlo, *gWhi, *gWlo, *gMhi, *gMlo;
    cudaGetSymbolAddress((void**)&gAhi, g_Ahi);
    cudaGetSymbolAddress((void**)&gAlo, g_Alo);
    cudaGetSymbolAddress((void**)&gBhi, g_Bhi);
    cudaGetSymbolAddress((void**)&gBlo, g_Blo);
    cudaGetSymbolAddress((void**)&gWhi, g_Whi);
    cudaGetSymbolAddress((void**)&gWlo, g_Wlo);
    cudaGetSymbolAddress((void**)&gMhi, g_Mhi);
    cudaGetSymbolAddress((void**)&gMlo, g_Mlo);

    cudaFuncSetAttribute(gemm_mma, cudaFuncAttributeMaxDynamicSharedMemorySize, SMEM_DYN);

    // lazily-created host-side handles (no device memory involved)
    static cudaStream_t sA = nullptr;
    static cudaEvent_t evFork = nullptr, evA = nullptr;
    if (!sA) {
        cudaStreamCreateWithFlags(&sA, cudaStreamNonBlocking);
        cudaEventCreateWithFlags(&evFork, cudaEventDisableTiming);
        cudaEventCreateWithFlags(&evA,    cudaEventDisableTiming);
    }

    // fork: side stream sA handles the edge-index chain
    cudaEventRecord(evFork, 0);
    cudaStreamWaitEvent(sA, evFork, 0);

    // stream A: zero -> count -> scan -> bucket
    zero_cnt_kernel<<<NKEY / 256, 256, 0, sA>>>();
    count_kernel<<<NEDGE / 256, 256, 0, sA>>>(ei, et);
    scan_kernel<<<1, 1024, 0, sA>>>();
    bucket_kernel<<<NEDGE / 256, 256, 0, sA>>>(ei, et);
    cudaEventRecord(evA, sA);

    // stream 0 (capture stream): ln + weight splits (independent of edge chain)
    ln_kernel<<<N_NODES, 256>>>(hidden, gamma, beta);
    split_kernel<<<2048, 256>>>(weight, gBhi, gBlo, (size_t)2048 * FINT / 4);
    split_kernel<<<1024, 256>>>(root, gBhi + (size_t)2048 * FINT, gBlo + (size_t)2048 * FINT,
                                (size_t)1024 * FINT / 4);
    split_kernel<<<1024, 256>>>(wo, gWhi, gWlo, (size_t)FINT * DMODEL / 4);

    // join: gather needs bucket (sA) + ln (s0)
    cudaStreamWaitEvent(0, evA, 0);
    gather_kernel<<<NKEY, 256>>>();

    // GEMM1: mid = relu(A[8192,3072] @ [weight;root][3072,4096] + bias) -> bf16 hi/lo
    gemm_mma<<<dim3(FINT / 256, N_NODES / 128), 256, SMEM_DYN>>>(
        gAhi, gAlo, KTOT, KTOT,
        gBhi, gBlo, FINT,
        bias, nullptr,
        nullptr, gMhi, gMlo, 1);

    // GEMM2: out = mid[8192,4096] @ wo[4096,1024] + hidden -> fp32
    gemm_mma<<<dim3(DMODEL / 256, N_NODES / 128), 256, SMEM_DYN>>>(
        gMhi, gMlo, FINT, FINT,
        gWhi, gWlo, DMODEL,
        nullptr, hidden,
        out, nullptr, nullptr, 2);
}

// round 9
// speedup vs baseline: 1.5297x; 1.3938x over previous
#include <cuda_runtime.h>
#include <cuda_fp16.h>
#include <cstdint>
#include <math.h>

#define N_NODES 8192
#define DMODEL 1024
#define FINT 4096
#define KTOT 3072
#define NEDGE 262144
#define NKEY (2 * N_NODES)
#define LN_EPS 1e-6f

// ---------------- PTX helpers (sm_80-era: valid on base compute_103) ---------
__device__ __forceinline__ uint32_t smem_u32(const void* p) {
    uint32_t a;
    asm("{ .reg .u64 t; cvta.to.shared.u64 t, %1; cvt.u32.u64 %0, t; }" : "=r"(a) : "l"(p));
    return a;
}
#define CP16(dst, src) asm volatile("cp.async.cg.shared.global [%0], [%1], 16;" :: "r"(dst), "l"(src))
#define CP_COMMIT()    asm volatile("cp.async.commit_group;" ::: "memory")
#define CP_WAIT1()     asm volatile("cp.async.wait_group 1;" ::: "memory")

__device__ __forceinline__ void ldsm4(uint32_t* r, uint32_t a) {
    asm volatile("ldmatrix.sync.aligned.m8n8.x4.shared.b16 {%0,%1,%2,%3}, [%4];"
                 : "=r"(r[0]), "=r"(r[1]), "=r"(r[2]), "=r"(r[3]) : "r"(a));
}
__device__ __forceinline__ void ldsm4t(uint32_t* r, uint32_t a) {
    asm volatile("ldmatrix.sync.aligned.m8n8.x4.trans.shared.b16 {%0,%1,%2,%3}, [%4];"
                 : "=r"(r[0]), "=r"(r[1]), "=r"(r[2]), "=r"(r[3]) : "r"(a));
}
__device__ __forceinline__ void mma16816(float* d, const uint32_t* a, const uint32_t* b) {
    asm volatile("mma.sync.aligned.m16n8k16.row.col.f32.f16.f16.f32 "
                 "{%0,%1,%2,%3}, {%4,%5,%6,%7}, {%8,%9}, {%0,%1,%2,%3};"
                 : "+f"(d[0]), "+f"(d[1]), "+f"(d[2]), "+f"(d[3])
                 : "r"(a[0]), "r"(a[1]), "r"(a[2]), "r"(a[3]), "r"(b[0]), "r"(b[1]));
}

// ---------------- scratch ----------------------------------------------------
__device__ float g_x[(size_t)N_NODES * DMODEL];
__device__ __half g_Ahi[(size_t)N_NODES * KTOT];           // A of GEMM1 (fp16, RN)
__device__ __half g_Bhi[(size_t)KTOT * FINT];               // [weight;root] hi
__device__ __half g_Blo[(size_t)KTOT * FINT];               // [weight;root] lo
__device__ __half g_Whi[(size_t)FINT * DMODEL];             // wo hi
__device__ __half g_Wlo[(size_t)FINT * DMODEL];             // wo lo
__device__ __half g_Mhi[(size_t)N_NODES * FINT];            // mid (fp16, RN)
__device__ int g_cnt[NKEY];
__device__ int g_off[NKEY];
__device__ int g_cur[NKEY];
__device__ int g_srcbuf[NEDGE];

// ---------------- helpers ------------------------------------------------------
__device__ __forceinline__ unsigned short h_rn(float x) {
    __half h = __float2half_rn(x);
    return *(unsigned short*)&h;
}
__device__ __forceinline__ void splitB2(float x0, float x1, ushort2& hv, ushort2& lv) {
    __half h0 = __float2half_rn(x0);
    __half h1 = __float2half_rn(x1);
    __half l0 = __float2half_rn(x0 - __half2float(h0));
    __half l1 = __float2half_rn(x1 - __half2float(h1));
    hv.x = *(unsigned short*)&h0; hv.y = *(unsigned short*)&h1;
    lv.x = *(unsigned short*)&l0; lv.y = *(unsigned short*)&l1;
}

// ---------------- pipeline kernels ---------------------------------------------
__global__ void zero_cnt_kernel() {
    int i = blockIdx.x * blockDim.x + threadIdx.x;
    if (i < NKEY) g_cnt[i] = 0;
}

__global__ __launch_bounds__(256) void ln_kernel(const float* __restrict__ hs,
                                                 const float* __restrict__ gamma,
                                                 const float* __restrict__ beta) {
    int n = blockIdx.x;
    int t = threadIdx.x;
    const float4 v = ((const float4*)(hs + (size_t)n * DMODEL))[t];
    float s  = v.x + v.y + v.z + v.w;
    float sq = v.x * v.x + v.y * v.y + v.z * v.z + v.w * v.w;
    __shared__ float red[16];
    for (int o = 16; o > 0; o >>= 1) {
        s  += __shfl_down_sync(0xffffffff, s,  o);
        sq += __shfl_down_sync(0xffffffff, sq, o);
    }
    int wid = t >> 5, lid = t & 31;
    if (lid == 0) { red[wid] = s; red[8 + wid] = sq; }
    __syncthreads();
    if (wid == 0) {
        s  = (lid < 8) ? red[lid]     : 0.f;
        sq = (lid < 8) ? red[8 + lid] : 0.f;
        for (int o = 4; o > 0; o >>= 1) {
            s  += __shfl_down_sync(0xffffffff, s,  o);
            sq += __shfl_down_sync(0xffffffff, sq, o);
        }
        if (lid == 0) { red[0] = s; red[1] = sq; }
    }
    __syncthreads();
    float mean = red[0] * (1.f / DMODEL);
    float var  = red[1] * (1.f / DMODEL) - mean * mean;
    float rstd = rsqrtf(var + LN_EPS);
    const float4 g = ((const float4*)gamma)[t];
    const float4 b = ((const float4*)beta)[t];
    float4 o;
    o.x = (v.x - mean) * rstd * g.x + b.x;
    o.y = (v.y - mean) * rstd * g.y + b.y;
    o.z = (v.z - mean) * rstd * g.z + b.z;
    o.w = (v.w - mean) * rstd * g.w + b.w;
    *(float4*)&g_x[(size_t)n * DMODEL + t * 4] = o;
    ushort4 hv = { h_rn(o.x), h_rn(o.y), h_rn(o.z), h_rn(o.w) };
    size_t a = ((size_t)n * KTOT + 2048) / 4 + t;
    ((ushort4*)g_Ahi)[a] = hv;
}

__global__ void count_kernel(const int* __restrict__ ei, const int* __restrict__ et) {
    int e = blockIdx.x * blockDim.x + threadIdx.x;
    if (e < NEDGE) atomicAdd(&g_cnt[et[e] * N_NODES + ei[NEDGE + e]], 1);
}

// two-level shfl scan over 16384 counts (1024 threads x 16)
__global__ __launch_bounds__(1024) void scan_kernel() {
    int tid = threadIdx.x;
    int lane = tid & 31, wid = tid >> 5;
    int base = tid * 16;
    int loc[16];
    int s = 0;
    #pragma unroll
    for (int i = 0; i < 16; i++) { loc[i] = s; s += g_cnt[base + i]; }
    int inc = s;
    #pragma unroll
    for (int o = 1; o < 32; o <<= 1) {
        int v = __shfl_up_sync(0xffffffff, inc, o);
        if (lane >= o) inc += v;
    }
    __shared__ int wtot[32];
    if (lane == 31) wtot[wid] = inc;
    __syncthreads();
    if (wid == 0) {
        int w = wtot[lane];
        int wi = w;
        #pragma unroll
        for (int o = 1; o < 32; o <<= 1) {
            int v = __shfl_up_sync(0xffffffff, wi, o);
            if (lane >= o) wi += v;
        }
        wtot[lane] = wi - w;
    }
    __syncthreads();
    int ex = wtot[wid] + (inc - s);
    #pragma unroll
    for (int i = 0; i < 16; i++) {
        int o = ex + loc[i];
        g_off[base + i] = o;
        g_cur[base + i] = o;
    }
}

__global__ void bucket_kernel(const int* __restrict__ ei, const int* __restrict__ et) {
    int e = blockIdx.x * blockDim.x + threadIdx.x;
    if (e < NEDGE) {
        int key = et[e] * N_NODES + ei[NEDGE + e];
        int pos = atomicAdd(&g_cur[key], 1);
        g_srcbuf[pos] = ei[e];
    }
}

__global__ __launch_bounds__(256) void gather_kernel() {
    int key = blockIdx.x;
    int node = key & (N_NODES - 1);
    int r = key >> 13;
    int off = g_off[key];
    int cnt = g_cnt[key];
    int c = threadIdx.x * 4;

    float4 acc = make_float4(0.f, 0.f, 0.f, 0.f);
    int i = 0;
    for (; i + 4 <= cnt; i += 4) {
        int s0 = g_srcbuf[off + i];
        int s1 = g_srcbuf[off + i + 1];
        int s2 = g_srcbuf[off + i + 2];
        int s3 = g_srcbuf[off + i + 3];
        float4 v0 = *(const float4*)&g_x[(size_t)s0 * DMODEL + c];
        float4 v1 = *(const float4*)&g_x[(size_t)s1 * DMODEL + c];
        float4 v2 = *(const float4*)&g_x[(size_t)s2 * DMODEL + c];
        float4 v3 = *(const float4*)&g_x[(size_t)s3 * DMODEL + c];
        acc.x += (v0.x + v1.x) + (v2.x + v3.x);
        acc.y += (v0.y + v1.y) + (v2.y + v3.y);
        acc.z += (v0.z + v1.z) + (v2.z + v3.z);
        acc.w += (v0.w + v1.w) + (v2.w + v3.w);
    }
    for (; i < cnt; i++) {
        int s0 = g_srcbuf[off + i];
        float4 v0 = *(const float4*)&g_x[(size_t)s0 * DMODEL + c];
        acc.x += v0.x; acc.y += v0.y; acc.z += v0.z; acc.w += v0.w;
    }
    float sc = 1.f / (float)max(cnt, 1);
    acc.x *= sc; acc.y *= sc; acc.z *= sc; acc.w *= sc;
    ushort4 hv = { h_rn(acc.x), h_rn(acc.y), h_rn(acc.z), h_rn(acc.w) };
    size_t a = ((size_t)node * KTOT + (size_t)r * 1024 + c) >> 2;
    ((ushort4*)g_Ahi)[a] = hv;
}

// B-side hi/lo split (weights)
__global__ void split_kernel(const float* __restrict__ src,
                             __half* __restrict__ hi,
                             __half* __restrict__ lo, size_t n4) {
    size_t i = (size_t)blockIdx.x * blockDim.x + threadIdx.x;
    for (; i < n4; i += (size_t)gridDim.x * blockDim.x) {
        float4 v = ((const float4*)src)[i];
        ushort2 h01, l01, h23, l23;
        splitB2(v.x, v.y, h01, l01);
        splitB2(v.z, v.w, h23, l23);
        ushort4 hv = { h01.x, h01.y, h23.x, h23.y };
        ushort4 lv = { l01.x, l01.y, l23.x, l23.y };
        ((ushort4*)hi)[i] = hv;
        ((ushort4*)lo)[i] = lv;
    }
}

// ---- fp16 2-term GEMM, CTA 128x256, warp 64x64: C = Ah*Bh + Ah*Bl -------------
// stage: Ahi 16K | Bhi 32K | Blo 32K = 80K; 2 stages = 160K
#define STAGE_BYTES 81920
#define OFF_BHI 16384
#define OFF_BLO 49152
#define SMEM_DYN (2 * STAGE_BYTES)
#define EPIPITCH 264

__device__ __forceinline__ uint32_t a_off(int row, int q) {
    return (uint32_t)(row * 128 + ((q ^ (row & 7)) << 4));
}
__device__ __forceinline__ uint32_t b_off(int row, int q) {
    return (uint32_t)(row * 512 + (((q & 24) | ((q & 7) ^ (row & 7))) << 4));
}

__global__ __launch_bounds__(256, 1) void gemm_mma(
    const __half* __restrict__ Ahi, int ldA, int K,
    const __half* __restrict__ Bhi, const __half* __restrict__ Blo, int ldB,
    const float* __restrict__ bias, const float* __restrict__ residual,
    float* __restrict__ outF, __half* __restrict__ outHi,
    int mode)
{
    extern __shared__ __align__(1024) char smem[];
    const uint32_t sb = smem_u32(smem);
    const int tid = threadIdx.x, wid = tid >> 5, lane = tid & 31;
    const int rowBase = blockIdx.y * 128;
    const int nBase   = blockIdx.x * 256;
    const int warp_m = (wid >> 2) * 64;
    const int warp_n = (wid & 3) * 64;
    const int lr = lane & 15, lc = lane >> 4;
    const int nchunk = K >> 6;

    float acc[4][8][4];
    #pragma unroll
    for (int i = 0; i < 4; i++)
        #pragma unroll
        for (int j = 0; j < 8; j++)
            #pragma unroll
            for (int k = 0; k < 4; k++) acc[i][j][k] = 0.f;

    auto load_chunk = [&](int c, int s) {
        const uint32_t sbase = sb + s * STAGE_BYTES;
        const int kb = c * 64;
        #pragma unroll
        for (int i = 0; i < 4; i++) {
            int v = tid + i * 256;
            int row = v >> 3, q = v & 7;
            uint32_t so = sbase + a_off(row, q);
            size_t g = (size_t)(rowBase + row) * ldA + kb + q * 8;
            CP16(so, Ahi + g);
        }
        #pragma unroll
        for (int i = 0; i < 8; i++) {
            int v = tid + i * 256;
            int row = v >> 5, q = v & 31;
            uint32_t so = sbase + OFF_BHI + b_off(row, q);
            size_t g = (size_t)(kb + row) * ldB + nBase + q * 8;
            CP16(so, Bhi + g);
            CP16(so + (OFF_BLO - OFF_BHI), Blo + g);
        }
    };

    load_chunk(0, 0); CP_COMMIT();
    load_chunk(1, 1); CP_COMMIT();

    for (int c = 0; c < nchunk; c++) {
        CP_WAIT1();
        __syncthreads();
        const uint32_t base = sb + (c & 1) * STAGE_BYTES;
        #pragma unroll
        for (int ks = 0; ks < 4; ks++) {
            uint32_t ah[4][4];
            #pragma unroll
            for (int mi = 0; mi < 4; mi++) {
                int row = warp_m + mi * 16 + lr;
                int q = ks * 2 + lc;
                ldsm4(ah[mi], base + a_off(row, q));
            }
            #pragma unroll
            for (int np = 0; np < 4; np++) {
                int row = ks * 16 + lr;
                int q = (warp_n >> 3) + np * 2 + lc;
                uint32_t addr = base + OFF_BHI + b_off(row, q);
                uint32_t th[4], tl[4];
                ldsm4t(th, addr);
                ldsm4t(tl, addr + (OFF_BLO - OFF_BHI));
                uint32_t bh0[2] = { th[0], th[1] }, bh1[2] = { th[2], th[3] };
                uint32_t bl0[2] = { tl[0], tl[1] }, bl1[2] = { tl[2], tl[3] };
                #pragma unroll
                for (int mi = 0; mi < 4; mi++) {
                    mma16816(acc[mi][np * 2], ah[mi], bh0);
                    mma16816(acc[mi][np * 2], ah[mi], bl0);
                    mma16816(acc[mi][np * 2 + 1], ah[mi], bh1);
                    mma16816(acc[mi][np * 2 + 1], ah[mi], bl1);
                }
            }
        }
        __syncthreads();
        if (c + 2 < nchunk) load_chunk(c + 2, c & 1);
        CP_COMMIT();
    }

    if (mode == 1) {
        unsigned short* stH = (unsigned short*)smem;
        #pragma unroll
        for (int mi = 0; mi < 4; mi++) {
            #pragma unroll
            for (int ni = 0; ni < 8; ni++) {
                int rl0 = warp_m + mi * 16 + (lane >> 2);
                int cl  = warp_n + ni * 8 + (lane & 3) * 2;
                #pragma unroll
                for (int h = 0; h < 2; h++) {
                    int rl = rl0 + h * 8;
                    float x0 = acc[mi][ni][h * 2 + 0];
                    float x1 = acc[mi][ni][h * 2 + 1];
                    int gc = nBase + cl;
                    x0 = fmaxf(x0 + bias[gc], 0.f);
                    x1 = fmaxf(x1 + bias[gc + 1], 0.f);
                    ushort2 hv = { h_rn(x0), h_rn(x1) };
                    *(ushort2*)&stH[rl * EPIPITCH + cl] = hv;
                }
            }
        }
        __syncthreads();
        #pragma unroll
        for (int i = 0; i < 16; i++) {
            int idx = tid + i * 256;
            int row = idx >> 5, ch = idx & 31;
            uint4 vh = *(uint4*)&stH[row * EPIPITCH + ch * 8];
            size_t go = (size_t)(rowBase + row) * ldB + nBase + ch * 8;
            *(uint4*)&outHi[go] = vh;
        }
    } else {
        #pragma unroll
        for (int mi = 0; mi < 4; mi++) {
            #pragma unroll
            for (int ni = 0; ni < 8; ni++) {
                int r0 = rowBase + warp_m + mi * 16 + (lane >> 2);
                int col = nBase + warp_n + ni * 8 + (lane & 3) * 2;
                #pragma unroll
                for (int h = 0; h < 2; h++) {
                    int row = r0 + h * 8;
                    float x0 = acc[mi][ni][h * 2 + 0];
                    float x1 = acc[mi][ni][h * 2 + 1];
                    size_t go = (size_t)row * ldB + col;
                    float2 res = *(const float2*)&residual[go];
                    float2 y = { x0 + res.x, x1 + res.y };
                    *(float2*)&outF[go] = y;
                }
            }
        }
    }
}

// ---------------- launch -------------------------------------------------------
extern "C" void kernel_launch(void* const* d_in, const int* in_sizes, int n_in,
                              void* d_out, int out_size) {
    const float* hidden = (const float*)d_in[0];
    const float* weight = (const float*)d_in[1];
    const float* root   = (const float*)d_in[2];
    const float* bias   = (const float*)d_in[3];
    const float* wo     = (const float*)d_in[4];
    const float* gamma  = (const float*)d_in[5];
    const float* beta   = (const float*)d_in[6];
    const int*   ei     = (const int*)d_in[7];
    const int*   et     = (const int*)d_in[8];
    float* out = (float*)d_out;

    __half *gAhi, *gBhi, *gBlo, *gWhi, *gWlo, *gMhi;
    cudaGetSymbolAddress((void**)&gAhi, g_Ahi);
    cudaGetSymbolAddress((void**)&gBhi, g_Bhi);
    cudaGetSymbolAddress((void**)&gBlo, g_Blo);
    cudaGetSymbolAddress((void**)&gWhi, g_Whi);
    cudaGetSymbolAddress((void**)&gWlo, g_Wlo);
    cudaGetSymbolAddress((void**)&gMhi, g_Mhi);

    cudaFuncSetAttribute(gemm_mma, cudaFuncAttributeMaxDynamicSharedMemorySize, SMEM_DYN);

    static cudaStream_t sA = nullptr;
    static cudaEvent_t evFork = nullptr, evA = nullptr;
    if (!sA) {
        cudaStreamCreateWithFlags(&sA, cudaStreamNonBlocking);
        cudaEventCreateWithFlags(&evFork, cudaEventDisableTiming);
        cudaEventCreateWithFlags(&evA,    cudaEventDisableTiming);
    }

    cudaEventRecord(evFork, 0);
    cudaStreamWaitEvent(sA, evFork, 0);

    // stream A: zero -> count -> scan -> bucket
    zero_cnt_kernel<<<NKEY / 256, 256, 0, sA>>>();
    count_kernel<<<NEDGE / 256, 256, 0, sA>>>(ei, et);
    scan_kernel<<<1, 1024, 0, sA>>>();
    bucket_kernel<<<NEDGE / 256, 256, 0, sA>>>(ei, et);
    cudaEventRecord(evA, sA);

    // stream 0: ln + weight splits
    ln_kernel<<<N_NODES, 256>>>(hidden, gamma, beta);
    split_kernel<<<2048, 256>>>(weight, gBhi, gBlo, (size_t)2048 * FINT / 4);
    split_kernel<<<1024, 256>>>(root, gBhi + (size_t)2048 * FINT, gBlo + (size_t)2048 * FINT,
                                (size_t)1024 * FINT / 4);
    split_kernel<<<1024, 256>>>(wo, gWhi, gWlo, (size_t)FINT * DMODEL / 4);

    cudaStreamWaitEvent(0, evA, 0);
    gather_kernel<<<NKEY, 256>>>();

    // GEMM1: mid = relu(A[8192,3072] @ [weight;root][3072,4096] + bias) -> fp16
    gemm_mma<<<dim3(FINT / 256, N_NODES / 128), 256, SMEM_DYN>>>(
        gAhi, KTOT, KTOT,
        gBhi, gBlo, FINT,
        bias, nullptr,
        nullptr, gMhi, 1);

    // GEMM2: out = mid[8192,4096] @ wo[4096,1024] + hidden -> fp32
    gemm_mma<<<dim3(DMODEL / 256, N_NODES / 128), 256, SMEM_DYN>>>(
        gMhi, FINT, FINT,
        gWhi, gWlo, DMODEL,
        nullptr, hidden,
        out, nullptr, 2);
}

// round 10
// speedup vs baseline: 2.5674x; 1.6784x over previous
#include <cuda_runtime.h>
#include <cuda_fp16.h>
#include <cstdint>
#include <math.h>

#define N_NODES 8192
#define DMODEL 1024
#define FINT 4096
#define KTOT 3072
#define NEDGE 262144
#define NKEY (2 * N_NODES)
#define LN_EPS 1e-6f

// ---------------- PTX helpers (sm_80-era: valid on base compute_103) ---------
__device__ __forceinline__ uint32_t smem_u32(const void* p) {
    uint32_t a;
    asm("{ .reg .u64 t; cvta.to.shared.u64 t, %1; cvt.u32.u64 %0, t; }" : "=r"(a) : "l"(p));
    return a;
}
#define CP16(dst, src) asm volatile("cp.async.cg.shared.global [%0], [%1], 16;" :: "r"(dst), "l"(src))
#define CP_COMMIT()    asm volatile("cp.async.commit_group;" ::: "memory")
#define CP_WAIT1()     asm volatile("cp.async.wait_group 1;" ::: "memory")

__device__ __forceinline__ void ldsm4(uint32_t* r, uint32_t a) {
    asm volatile("ldmatrix.sync.aligned.m8n8.x4.shared.b16 {%0,%1,%2,%3}, [%4];"
                 : "=r"(r[0]), "=r"(r[1]), "=r"(r[2]), "=r"(r[3]) : "r"(a));
}
__device__ __forceinline__ void ldsm4t(uint32_t* r, uint32_t a) {
    asm volatile("ldmatrix.sync.aligned.m8n8.x4.trans.shared.b16 {%0,%1,%2,%3}, [%4];"
                 : "=r"(r[0]), "=r"(r[1]), "=r"(r[2]), "=r"(r[3]) : "r"(a));
}
__device__ __forceinline__ void mma16816(float* d, const uint32_t* a, const uint32_t* b) {
    asm volatile("mma.sync.aligned.m16n8k16.row.col.f32.f16.f16.f32 "
                 "{%0,%1,%2,%3}, {%4,%5,%6,%7}, {%8,%9}, {%0,%1,%2,%3};"
                 : "+f"(d[0]), "+f"(d[1]), "+f"(d[2]), "+f"(d[3])
                 : "r"(a[0]), "r"(a[1]), "r"(a[2]), "r"(a[3]), "r"(b[0]), "r"(b[1]));
}

// ---------------- scratch ----------------------------------------------------
__device__ float g_x[(size_t)N_NODES * DMODEL];
__device__ __half g_Ahi[(size_t)N_NODES * KTOT];   // A of GEMM1 (fp16 RN)
__device__ __half g_Bhi[(size_t)KTOT * FINT];       // [weight;root] fp16
__device__ __half g_Whi[(size_t)FINT * DMODEL];     // wo fp16
__device__ __half g_Mhi[(size_t)N_NODES * FINT];    // mid fp16
__device__ int g_cnt[NKEY];
__device__ int g_off[NKEY];
__device__ int g_cur[NKEY];
__device__ int g_srcbuf[NEDGE];

// ---------------- helpers ------------------------------------------------------
__device__ __forceinline__ unsigned short h_rn(float x) {
    __half h = __float2half_rn(x);
    return *(unsigned short*)&h;
}

// ---------------- pipeline kernels ---------------------------------------------
__global__ void zero_cnt_kernel() {
    int i = blockIdx.x * blockDim.x + threadIdx.x;
    if (i < NKEY) g_cnt[i] = 0;
}

__global__ __launch_bounds__(256) void ln_kernel(const float* __restrict__ hs,
                                                 const float* __restrict__ gamma,
                                                 const float* __restrict__ beta) {
    int n = blockIdx.x;
    int t = threadIdx.x;
    const float4 v = ((const float4*)(hs + (size_t)n * DMODEL))[t];
    float s  = v.x + v.y + v.z + v.w;
    float sq = v.x * v.x + v.y * v.y + v.z * v.z + v.w * v.w;
    __shared__ float red[16];
    for (int o = 16; o > 0; o >>= 1) {
        s  += __shfl_down_sync(0xffffffff, s,  o);
        sq += __shfl_down_sync(0xffffffff, sq, o);
    }
    int wid = t >> 5, lid = t & 31;
    if (lid == 0) { red[wid] = s; red[8 + wid] = sq; }
    __syncthreads();
    if (wid == 0) {
        s  = (lid < 8) ? red[lid]     : 0.f;
        sq = (lid < 8) ? red[8 + lid] : 0.f;
        for (int o = 4; o > 0; o >>= 1) {
            s  += __shfl_down_sync(0xffffffff, s,  o);
            sq += __shfl_down_sync(0xffffffff, sq, o);
        }
        if (lid == 0) { red[0] = s; red[1] = sq; }
    }
    __syncthreads();
    float mean = red[0] * (1.f / DMODEL);
    float var  = red[1] * (1.f / DMODEL) - mean * mean;
    float rstd = rsqrtf(var + LN_EPS);
    const float4 g = ((const float4*)gamma)[t];
    const float4 b = ((const float4*)beta)[t];
    float4 o;
    o.x = (v.x - mean) * rstd * g.x + b.x;
    o.y = (v.y - mean) * rstd * g.y + b.y;
    o.z = (v.z - mean) * rstd * g.z + b.z;
    o.w = (v.w - mean) * rstd * g.w + b.w;
    *(float4*)&g_x[(size_t)n * DMODEL + t * 4] = o;
    ushort4 hv = { h_rn(o.x), h_rn(o.y), h_rn(o.z), h_rn(o.w) };
    size_t a = ((size_t)n * KTOT + 2048) / 4 + t;
    ((ushort4*)g_Ahi)[a] = hv;
}

__global__ void count_kernel(const int* __restrict__ ei, const int* __restrict__ et) {
    int e = blockIdx.x * blockDim.x + threadIdx.x;
    if (e < NEDGE) atomicAdd(&g_cnt[et[e] * N_NODES + ei[NEDGE + e]], 1);
}

// two-level shfl scan over 16384 counts (1024 threads x 16)
__global__ __launch_bounds__(1024) void scan_kernel() {
    int tid = threadIdx.x;
    int lane = tid & 31, wid = tid >> 5;
    int base = tid * 16;
    int loc[16];
    int s = 0;
    #pragma unroll
    for (int i = 0; i < 16; i++) { loc[i] = s; s += g_cnt[base + i]; }
    int inc = s;
    #pragma unroll
    for (int o = 1; o < 32; o <<= 1) {
        int v = __shfl_up_sync(0xffffffff, inc, o);
        if (lane >= o) inc += v;
    }
    __shared__ int wtot[32];
    if (lane == 31) wtot[wid] = inc;
    __syncthreads();
    if (wid == 0) {
        int w = wtot[lane];
        int wi = w;
        #pragma unroll
        for (int o = 1; o < 32; o <<= 1) {
            int v = __shfl_up_sync(0xffffffff, wi, o);
            if (lane >= o) wi += v;
        }
        wtot[lane] = wi - w;
    }
    __syncthreads();
    int ex = wtot[wid] + (inc - s);
    #pragma unroll
    for (int i = 0; i < 16; i++) {
        int o = ex + loc[i];
        g_off[base + i] = o;
        g_cur[base + i] = o;
    }
}

__global__ void bucket_kernel(const int* __restrict__ ei, const int* __restrict__ et) {
    int e = blockIdx.x * blockDim.x + threadIdx.x;
    if (e < NEDGE) {
        int key = et[e] * N_NODES + ei[NEDGE + e];
        int pos = atomicAdd(&g_cur[key], 1);
        g_srcbuf[pos] = ei[e];
    }
}

__global__ __launch_bounds__(256) void gather_kernel() {
    int key = blockIdx.x;
    int node = key & (N_NODES - 1);
    int r = key >> 13;
    int off = g_off[key];
    int cnt = g_cnt[key];
    int c = threadIdx.x * 4;

    float4 acc = make_float4(0.f, 0.f, 0.f, 0.f);
    int i = 0;
    for (; i + 4 <= cnt; i += 4) {
        int s0 = g_srcbuf[off + i];
        int s1 = g_srcbuf[off + i + 1];
        int s2 = g_srcbuf[off + i + 2];
        int s3 = g_srcbuf[off + i + 3];
        float4 v0 = *(const float4*)&g_x[(size_t)s0 * DMODEL + c];
        float4 v1 = *(const float4*)&g_x[(size_t)s1 * DMODEL + c];
        float4 v2 = *(const float4*)&g_x[(size_t)s2 * DMODEL + c];
        float4 v3 = *(const float4*)&g_x[(size_t)s3 * DMODEL + c];
        acc.x += (v0.x + v1.x) + (v2.x + v3.x);
        acc.y += (v0.y + v1.y) + (v2.y + v3.y);
        acc.z += (v0.z + v1.z) + (v2.z + v3.z);
        acc.w += (v0.w + v1.w) + (v2.w + v3.w);
    }
    for (; i < cnt; i++) {
        int s0 = g_srcbuf[off + i];
        float4 v0 = *(const float4*)&g_x[(size_t)s0 * DMODEL + c];
        acc.x += v0.x; acc.y += v0.y; acc.z += v0.z; acc.w += v0.w;
    }
    float sc = 1.f / (float)max(cnt, 1);
    acc.x *= sc; acc.y *= sc; acc.z *= sc; acc.w *= sc;
    ushort4 hv = { h_rn(acc.x), h_rn(acc.y), h_rn(acc.z), h_rn(acc.w) };
    size_t a = ((size_t)node * KTOT + (size_t)r * 1024 + c) >> 2;
    ((ushort4*)g_Ahi)[a] = hv;
}

// fp32 -> fp16 convert
__global__ void cvt_kernel(const float* __restrict__ src,
                           __half* __restrict__ dst, size_t n4) {
    size_t i = (size_t)blockIdx.x * blockDim.x + threadIdx.x;
    for (; i < n4; i += (size_t)gridDim.x * blockDim.x) {
        float4 v = ((const float4*)src)[i];
        ushort4 hv = { h_rn(v.x), h_rn(v.y), h_rn(v.z), h_rn(v.w) };
        ((ushort4*)dst)[i] = hv;
    }
}

// ---- pure fp16 GEMM, CTA 128x256, warp 64x64: C = A*B ------------------------
// stage: A 16K | B 32K = 48K; 2 stages = 96K
#define STAGE_BYTES 49152
#define OFF_BHI 16384
#define SMEM_DYN (2 * STAGE_BYTES)
#define EPIPITCH 264

__device__ __forceinline__ uint32_t a_off(int row, int q) {
    return (uint32_t)(row * 128 + ((q ^ (row & 7)) << 4));
}
__device__ __forceinline__ uint32_t b_off(int row, int q) {
    return (uint32_t)(row * 512 + (((q & 24) | ((q & 7) ^ (row & 7))) << 4));
}

__global__ __launch_bounds__(256, 1) void gemm_mma(
    const __half* __restrict__ A, int ldA, int K,
    const __half* __restrict__ B, int ldB,
    const float* __restrict__ bias, const float* __restrict__ residual,
    float* __restrict__ outF, __half* __restrict__ outH,
    int mode)
{
    extern __shared__ __align__(1024) char smem[];
    const uint32_t sb = smem_u32(smem);
    const int tid = threadIdx.x, wid = tid >> 5, lane = tid & 31;
    const int rowBase = blockIdx.y * 128;
    const int nBase   = blockIdx.x * 256;
    const int warp_m = (wid >> 2) * 64;
    const int warp_n = (wid & 3) * 64;
    const int lr = lane & 15, lc = lane >> 4;
    const int nchunk = K >> 6;

    float acc[4][8][4];
    #pragma unroll
    for (int i = 0; i < 4; i++)
        #pragma unroll
        for (int j = 0; j < 8; j++)
            #pragma unroll
            for (int k = 0; k < 4; k++) acc[i][j][k] = 0.f;

    auto load_chunk = [&](int c, int s) {
        const uint32_t sbase = sb + s * STAGE_BYTES;
        const int kb = c * 64;
        #pragma unroll
        for (int i = 0; i < 4; i++) {
            int v = tid + i * 256;
            int row = v >> 3, q = v & 7;
            uint32_t so = sbase + a_off(row, q);
            size_t g = (size_t)(rowBase + row) * ldA + kb + q * 8;
            CP16(so, A + g);
        }
        #pragma unroll
        for (int i = 0; i < 8; i++) {
            int v = tid + i * 256;
            int row = v >> 5, q = v & 31;
            uint32_t so = sbase + OFF_BHI + b_off(row, q);
            size_t g = (size_t)(kb + row) * ldB + nBase + q * 8;
            CP16(so, B + g);
        }
    };

    load_chunk(0, 0); CP_COMMIT();
    load_chunk(1, 1); CP_COMMIT();

    for (int c = 0; c < nchunk; c++) {
        CP_WAIT1();
        __syncthreads();
        const uint32_t base = sb + (c & 1) * STAGE_BYTES;
        #pragma unroll
        for (int ks = 0; ks < 4; ks++) {
            uint32_t ah[4][4];
            #pragma unroll
            for (int mi = 0; mi < 4; mi++) {
                int row = warp_m + mi * 16 + lr;
                int q = ks * 2 + lc;
                ldsm4(ah[mi], base + a_off(row, q));
            }
            #pragma unroll
            for (int np = 0; np < 4; np++) {
                int row = ks * 16 + lr;
                int q = (warp_n >> 3) + np * 2 + lc;
                uint32_t th[4];
                ldsm4t(th, base + OFF_BHI + b_off(row, q));
                uint32_t b0[2] = { th[0], th[1] }, b1[2] = { th[2], th[3] };
                #pragma unroll
                for (int mi = 0; mi < 4; mi++) {
                    mma16816(acc[mi][np * 2], ah[mi], b0);
                    mma16816(acc[mi][np * 2 + 1], ah[mi], b1);
                }
            }
        }
        __syncthreads();
        if (c + 2 < nchunk) load_chunk(c + 2, c & 1);
        CP_COMMIT();
    }

    if (mode == 1) {
        unsigned short* stH = (unsigned short*)smem;
        #pragma unroll
        for (int mi = 0; mi < 4; mi++) {
            #pragma unroll
            for (int ni = 0; ni < 8; ni++) {
                int rl0 = warp_m + mi * 16 + (lane >> 2);
                int cl  = warp_n + ni * 8 + (lane & 3) * 2;
                #pragma unroll
                for (int h = 0; h < 2; h++) {
                    int rl = rl0 + h * 8;
                    float x0 = acc[mi][ni][h * 2 + 0];
                    float x1 = acc[mi][ni][h * 2 + 1];
                    int gc = nBase + cl;
                    x0 = fmaxf(x0 + bias[gc], 0.f);
                    x1 = fmaxf(x1 + bias[gc + 1], 0.f);
                    ushort2 hv = { h_rn(x0), h_rn(x1) };
                    *(ushort2*)&stH[rl * EPIPITCH + cl] = hv;
                }
            }
        }
        __syncthreads();
        #pragma unroll
        for (int i = 0; i < 16; i++) {
            int idx = tid + i * 256;
            int row = idx >> 5, ch = idx & 31;
            uint4 vh = *(uint4*)&stH[row * EPIPITCH + ch * 8];
            size_t go = (size_t)(rowBase + row) * ldB + nBase + ch * 8;
            *(uint4*)&outH[go] = vh;
        }
    } else {
        #pragma unroll
        for (int mi = 0; mi < 4; mi++) {
            #pragma unroll
            for (int ni = 0; ni < 8; ni++) {
                int r0 = rowBase + warp_m + mi * 16 + (lane >> 2);
                int col = nBase + warp_n + ni * 8 + (lane & 3) * 2;
                #pragma unroll
                for (int h = 0; h < 2; h++) {
                    int row = r0 + h * 8;
                    float x0 = acc[mi][ni][h * 2 + 0];
                    float x1 = acc[mi][ni][h * 2 + 1];
                    size_t go = (size_t)row * ldB + col;
                    float2 res = *(const float2*)&residual[go];
                    float2 y = { x0 + res.x, x1 + res.y };
                    *(float2*)&outF[go] = y;
                }
            }
        }
    }
}

// ---------------- launch -------------------------------------------------------
extern "C" void kernel_launch(void* const* d_in, const int* in_sizes, int n_in,
                              void* d_out, int out_size) {
    const float* hidden = (const float*)d_in[0];
    const float* weight = (const float*)d_in[1];
    const float* root   = (const float*)d_in[2];
    const float* bias   = (const float*)d_in[3];
    const float* wo     = (const float*)d_in[4];
    const float* gamma  = (const float*)d_in[5];
    const float* beta   = (const float*)d_in[6];
    const int*   ei     = (const int*)d_in[7];
    const int*   et     = (const int*)d_in[8];
    float* out = (float*)d_out;

    __half *gAhi, *gBhi, *gWhi, *gMhi;
    cudaGetSymbolAddress((void**)&gAhi, g_Ahi);
    cudaGetSymbolAddress((void**)&gBhi, g_Bhi);
    cudaGetSymbolAddress((void**)&gWhi, g_Whi);
    cudaGetSymbolAddress((void**)&gMhi, g_Mhi);

    cudaFuncSetAttribute(gemm_mma, cudaFuncAttributeMaxDynamicSharedMemorySize, SMEM_DYN);

    static cudaStream_t sA = nullptr;
    static cudaEvent_t evFork = nullptr, evA = nullptr;
    if (!sA) {
        cudaStreamCreateWithFlags(&sA, cudaStreamNonBlocking);
        cudaEventCreateWithFlags(&evFork, cudaEventDisableTiming);
        cudaEventCreateWithFlags(&evA,    cudaEventDisableTiming);
    }

    cudaEventRecord(evFork, 0);
    cudaStreamWaitEvent(sA, evFork, 0);

    // stream A: zero -> count -> scan -> bucket
    zero_cnt_kernel<<<NKEY / 256, 256, 0, sA>>>();
    count_kernel<<<NEDGE / 256, 256, 0, sA>>>(ei, et);
    scan_kernel<<<1, 1024, 0, sA>>>();
    bucket_kernel<<<NEDGE / 256, 256, 0, sA>>>(ei, et);
    cudaEventRecord(evA, sA);

    // stream 0: ln + weight converts
    ln_kernel<<<N_NODES, 256>>>(hidden, gamma, beta);
    cvt_kernel<<<2048, 256>>>(weight, gBhi, (size_t)2048 * FINT / 4);
    cvt_kernel<<<1024, 256>>>(root, gBhi + (size_t)2048 * FINT, (size_t)1024 * FINT / 4);
    cvt_kernel<<<1024, 256>>>(wo, gWhi, (size_t)FINT * DMODEL / 4);

    cudaStreamWaitEvent(0, evA, 0);
    gather_kernel<<<NKEY, 256>>>();

    // GEMM1: mid = relu(A[8192,3072] @ [weight;root][3072,4096] + bias) -> fp16
    gemm_mma<<<dim3(FINT / 256, N_NODES / 128), 256, SMEM_DYN>>>(
        gAhi, KTOT, KTOT,
        gBhi, FINT,
        bias, nullptr,
        nullptr, gMhi, 1);

    // GEMM2: out = mid[8192,4096] @ wo[4096,1024] + hidden -> fp32
    gemm_mma<<<dim3(DMODEL / 256, N_NODES / 128), 256, SMEM_DYN>>>(
        gMhi, FINT, FINT,
        gWhi, DMODEL,
        nullptr, hidden,
        out, nullptr, 2);
}

// round 11
// speedup vs baseline: 2.6044x; 1.0144x over previous
#include <cuda_runtime.h>
#include <cuda_fp16.h>
#include <cstdint>
#include <math.h>

#define N_NODES 8192
#define DMODEL 1024
#define FINT 4096
#define KTOT 3072
#define NEDGE 262144
#define NKEY (2 * N_NODES)
#define LN_EPS 1e-6f

// ---------------- PTX helpers (sm_80-era: valid on base compute_103) ---------
__device__ __forceinline__ uint32_t smem_u32(const void* p) {
    uint32_t a;
    asm("{ .reg .u64 t; cvta.to.shared.u64 t, %1; cvt.u32.u64 %0, t; }" : "=r"(a) : "l"(p));
    return a;
}
#define CP16(dst, src) asm volatile("cp.async.cg.shared.global [%0], [%1], 16;" :: "r"(dst), "l"(src))
#define CP_COMMIT()    asm volatile("cp.async.commit_group;" ::: "memory")
#define CP_WAIT2()     asm volatile("cp.async.wait_group 2;" ::: "memory")

__device__ __forceinline__ void ldsm4(uint32_t* r, uint32_t a) {
    asm volatile("ldmatrix.sync.aligned.m8n8.x4.shared.b16 {%0,%1,%2,%3}, [%4];"
                 : "=r"(r[0]), "=r"(r[1]), "=r"(r[2]), "=r"(r[3]) : "r"(a));
}
__device__ __forceinline__ void ldsm4t(uint32_t* r, uint32_t a) {
    asm volatile("ldmatrix.sync.aligned.m8n8.x4.trans.shared.b16 {%0,%1,%2,%3}, [%4];"
                 : "=r"(r[0]), "=r"(r[1]), "=r"(r[2]), "=r"(r[3]) : "r"(a));
}
__device__ __forceinline__ void mma16816(float* d, const uint32_t* a, const uint32_t* b) {
    asm volatile("mma.sync.aligned.m16n8k16.row.col.f32.f16.f16.f32 "
                 "{%0,%1,%2,%3}, {%4,%5,%6,%7}, {%8,%9}, {%0,%1,%2,%3};"
                 : "+f"(d[0]), "+f"(d[1]), "+f"(d[2]), "+f"(d[3])
                 : "r"(a[0]), "r"(a[1]), "r"(a[2]), "r"(a[3]), "r"(b[0]), "r"(b[1]));
}

// ---------------- scratch ----------------------------------------------------
__device__ __half g_xh[(size_t)N_NODES * DMODEL];   // LN output, compact fp16
__device__ __half g_Ahi[(size_t)N_NODES * KTOT];
__device__ __half g_Bhi[(size_t)KTOT * FINT];
__device__ __half g_Whi[(size_t)FINT * DMODEL];
__device__ __half g_Mhi[(size_t)N_NODES * FINT];
__device__ int g_cnt[NKEY];
__device__ int g_off[NKEY];
__device__ int g_cur[NKEY];
__device__ int g_srcbuf[NEDGE];

__device__ __forceinline__ unsigned short h_rn(float x) {
    __half h = __float2half_rn(x);
    return *(unsigned short*)&h;
}

// ---------------- pipeline kernels ---------------------------------------------
__global__ void zero_cnt_kernel() {
    int i = blockIdx.x * blockDim.x + threadIdx.x;
    if (i < NKEY) g_cnt[i] = 0;
}

__global__ __launch_bounds__(256) void ln_kernel(const float* __restrict__ hs,
                                                 const float* __restrict__ gamma,
                                                 const float* __restrict__ beta) {
    int n = blockIdx.x;
    int t = threadIdx.x;
    const float4 v = ((const float4*)(hs + (size_t)n * DMODEL))[t];
    float s  = v.x + v.y + v.z + v.w;
    float sq = v.x * v.x + v.y * v.y + v.z * v.z + v.w * v.w;
    __shared__ float red[16];
    for (int o = 16; o > 0; o >>= 1) {
        s  += __shfl_down_sync(0xffffffff, s,  o);
        sq += __shfl_down_sync(0xffffffff, sq, o);
    }
    int wid = t >> 5, lid = t & 31;
    if (lid == 0) { red[wid] = s; red[8 + wid] = sq; }
    __syncthreads();
    if (wid == 0) {
        s  = (lid < 8) ? red[lid]     : 0.f;
        sq = (lid < 8) ? red[8 + lid] : 0.f;
        for (int o = 4; o > 0; o >>= 1) {
            s  += __shfl_down_sync(0xffffffff, s,  o);
            sq += __shfl_down_sync(0xffffffff, sq, o);
        }
        if (lid == 0) { red[0] = s; red[1] = sq; }
    }
    __syncthreads();
    float mean = red[0] * (1.f / DMODEL);
    float var  = red[1] * (1.f / DMODEL) - mean * mean;
    float rstd = rsqrtf(var + LN_EPS);
    const float4 g = ((const float4*)gamma)[t];
    const float4 b = ((const float4*)beta)[t];
    float4 o;
    o.x = (v.x - mean) * rstd * g.x + b.x;
    o.y = (v.y - mean) * rstd * g.y + b.y;
    o.z = (v.z - mean) * rstd * g.z + b.z;
    o.w = (v.w - mean) * rstd * g.w + b.w;
    ushort4 hv = { h_rn(o.x), h_rn(o.y), h_rn(o.z), h_rn(o.w) };
    ((ushort4*)g_xh)[(size_t)n * (DMODEL / 4) + t] = hv;
    size_t a = ((size_t)n * KTOT + 2048) / 4 + t;
    ((ushort4*)g_Ahi)[a] = hv;
}

__global__ void count_kernel(const int* __restrict__ ei, const int* __restrict__ et) {
    int e = blockIdx.x * blockDim.x + threadIdx.x;
    if (e < NEDGE) atomicAdd(&g_cnt[et[e] * N_NODES + ei[NEDGE + e]], 1);
}

// two-level shfl scan over 16384 counts (1024 threads x 16)
__global__ __launch_bounds__(1024) void scan_kernel() {
    int tid = threadIdx.x;
    int lane = tid & 31, wid = tid >> 5;
    int base = tid * 16;
    int loc[16];
    int s = 0;
    #pragma unroll
    for (int i = 0; i < 16; i++) { loc[i] = s; s += g_cnt[base + i]; }
    int inc = s;
    #pragma unroll
    for (int o = 1; o < 32; o <<= 1) {
        int v = __shfl_up_sync(0xffffffff, inc, o);
        if (lane >= o) inc += v;
    }
    __shared__ int wtot[32];
    if (lane == 31) wtot[wid] = inc;
    __syncthreads();
    if (wid == 0) {
        int w = wtot[lane];
        int wi = w;
        #pragma unroll
        for (int o = 1; o < 32; o <<= 1) {
            int v = __shfl_up_sync(0xffffffff, wi, o);
            if (lane >= o) wi += v;
        }
        wtot[lane] = wi - w;
    }
    __syncthreads();
    int ex = wtot[wid] + (inc - s);
    #pragma unroll
    for (int i = 0; i < 16; i++) {
        int o = ex + loc[i];
        g_off[base + i] = o;
        g_cur[base + i] = o;
    }
}

__global__ void bucket_kernel(const int* __restrict__ ei, const int* __restrict__ et) {
    int e = blockIdx.x * blockDim.x + threadIdx.x;
    if (e < NEDGE) {
        int key = et[e] * N_NODES + ei[NEDGE + e];
        int pos = atomicAdd(&g_cur[key], 1);
        g_srcbuf[pos] = ei[e];
    }
}

// 128 threads/CTA, each owns 8 columns; reads fp16 rows (uint4 = 8 halves)
__global__ __launch_bounds__(128) void gather_kernel() {
    int key = blockIdx.x;
    int node = key & (N_NODES - 1);
    int r = key >> 13;
    int off = g_off[key];
    int cnt = g_cnt[key];
    int t = threadIdx.x;   // 0..127

    float2 acc[4] = { {0.f,0.f}, {0.f,0.f}, {0.f,0.f}, {0.f,0.f} };
    const uint4* xrow = (const uint4*)g_xh;  // row stride = 1024/8 = 128 uint4
    int i = 0;
    for (; i + 2 <= cnt; i += 2) {
        int s0 = g_srcbuf[off + i];
        int s1 = g_srcbuf[off + i + 1];
        uint4 v0 = xrow[(size_t)s0 * 128 + t];
        uint4 v1 = xrow[(size_t)s1 * 128 + t];
        const __half2* h0 = (const __half2*)&v0;
        const __half2* h1 = (const __half2*)&v1;
        #pragma unroll
        for (int j = 0; j < 4; j++) {
            float2 f0 = __half22float2(h0[j]);
            float2 f1 = __half22float2(h1[j]);
            acc[j].x += f0.x + f1.x;
            acc[j].y += f0.y + f1.y;
        }
    }
    if (i < cnt) {
        int s0 = g_srcbuf[off + i];
        uint4 v0 = xrow[(size_t)s0 * 128 + t];
        const __half2* h0 = (const __half2*)&v0;
        #pragma unroll
        for (int j = 0; j < 4; j++) {
            float2 f0 = __half22float2(h0[j]);
            acc[j].x += f0.x;
            acc[j].y += f0.y;
        }
    }
    float sc = 1.f / (float)max(cnt, 1);
    ushort4 o0, o1;
    o0.x = h_rn(acc[0].x * sc); o0.y = h_rn(acc[0].y * sc);
    o0.z = h_rn(acc[1].x * sc); o0.w = h_rn(acc[1].y * sc);
    o1.x = h_rn(acc[2].x * sc); o1.y = h_rn(acc[2].y * sc);
    o1.z = h_rn(acc[3].x * sc); o1.w = h_rn(acc[3].y * sc);
    size_t a = ((size_t)node * KTOT + (size_t)r * 1024 + t * 8) >> 2;
    ((ushort4*)g_Ahi)[a] = o0;
    ((ushort4*)g_Ahi)[a + 1] = o1;
}

// fp32 -> fp16 convert
__global__ void cvt_kernel(const float* __restrict__ src,
                           __half* __restrict__ dst, size_t n4) {
    size_t i = (size_t)blockIdx.x * blockDim.x + threadIdx.x;
    for (; i < n4; i += (size_t)gridDim.x * blockDim.x) {
        float4 v = ((const float4*)src)[i];
        ushort4 hv = { h_rn(v.x), h_rn(v.y), h_rn(v.z), h_rn(v.w) };
        ((ushort4*)dst)[i] = hv;
    }
}

// ---- pure fp16 GEMM, CTA 128x256, warp 64x64, 3-stage cp.async ---------------
#define STAGE_BYTES 49152
#define OFF_BHI 16384
#define NSTAGE 3
#define SMEM_DYN (NSTAGE * STAGE_BYTES)
#define EPIPITCH 264

__device__ __forceinline__ uint32_t a_off(int row, int q) {
    return (uint32_t)(row * 128 + ((q ^ (row & 7)) << 4));
}
__device__ __forceinline__ uint32_t b_off(int row, int q) {
    return (uint32_t)(row * 512 + (((q & 24) | ((q & 7) ^ (row & 7))) << 4));
}

__global__ __launch_bounds__(256, 1) void gemm_mma(
    const __half* __restrict__ A, int ldA, int K,
    const __half* __restrict__ B, int ldB,
    const float* __restrict__ bias, const float* __restrict__ residual,
    float* __restrict__ outF, __half* __restrict__ outH,
    int mode)
{
    extern __shared__ __align__(1024) char smem[];
    const uint32_t sb = smem_u32(smem);
    const int tid = threadIdx.x, wid = tid >> 5, lane = tid & 31;
    const int rowBase = blockIdx.y * 128;
    const int nBase   = blockIdx.x * 256;
    const int warp_m = (wid >> 2) * 64;
    const int warp_n = (wid & 3) * 64;
    const int lr = lane & 15, lc = lane >> 4;
    const int nchunk = K >> 6;

    float acc[4][8][4];
    #pragma unroll
    for (int i = 0; i < 4; i++)
        #pragma unroll
        for (int j = 0; j < 8; j++)
            #pragma unroll
            for (int k = 0; k < 4; k++) acc[i][j][k] = 0.f;

    auto load_chunk = [&](int c, int s) {
        const uint32_t sbase = sb + s * STAGE_BYTES;
        const int kb = c * 64;
        #pragma unroll
        for (int i = 0; i < 4; i++) {
            int v = tid + i * 256;
            int row = v >> 3, q = v & 7;
            uint32_t so = sbase + a_off(row, q);
            size_t g = (size_t)(rowBase + row) * ldA + kb + q * 8;
            CP16(so, A + g);
        }
        #pragma unroll
        for (int i = 0; i < 8; i++) {
            int v = tid + i * 256;
            int row = v >> 5, q = v & 31;
            uint32_t so = sbase + OFF_BHI + b_off(row, q);
            size_t g = (size_t)(kb + row) * ldB + nBase + q * 8;
            CP16(so, B + g);
        }
    };

    load_chunk(0, 0); CP_COMMIT();
    load_chunk(1, 1); CP_COMMIT();
    load_chunk(2, 2); CP_COMMIT();

    for (int c = 0; c < nchunk; c++) {
        CP_WAIT2();
        __syncthreads();
        const int slot = c % NSTAGE;
        const uint32_t base = sb + slot * STAGE_BYTES;
        #pragma unroll
        for (int ks = 0; ks < 4; ks++) {
            uint32_t ah[4][4];
            #pragma unroll
            for (int mi = 0; mi < 4; mi++) {
                int row = warp_m + mi * 16 + lr;
                int q = ks * 2 + lc;
                ldsm4(ah[mi], base + a_off(row, q));
            }
            #pragma unroll
            for (int np = 0; np < 4; np++) {
                int row = ks * 16 + lr;
                int q = (warp_n >> 3) + np * 2 + lc;
                uint32_t th[4];
                ldsm4t(th, base + OFF_BHI + b_off(row, q));
                uint32_t b0[2] = { th[0], th[1] }, b1[2] = { th[2], th[3] };
                #pragma unroll
                for (int mi = 0; mi < 4; mi++) {
                    mma16816(acc[mi][np * 2], ah[mi], b0);
                    mma16816(acc[mi][np * 2 + 1], ah[mi], b1);
                }
            }
        }
        __syncthreads();
        if (c + NSTAGE < nchunk) load_chunk(c + NSTAGE, slot);
        CP_COMMIT();
    }

    if (mode == 1) {
        unsigned short* stH = (unsigned short*)smem;
        #pragma unroll
        for (int mi = 0; mi < 4; mi++) {
            #pragma unroll
            for (int ni = 0; ni < 8; ni++) {
                int rl0 = warp_m + mi * 16 + (lane >> 2);
                int cl  = warp_n + ni * 8 + (lane & 3) * 2;
                #pragma unroll
                for (int h = 0; h < 2; h++) {
                    int rl = rl0 + h * 8;
                    float x0 = acc[mi][ni][h * 2 + 0];
                    float x1 = acc[mi][ni][h * 2 + 1];
                    int gc = nBase + cl;
                    x0 = fmaxf(x0 + bias[gc], 0.f);
                    x1 = fmaxf(x1 + bias[gc + 1], 0.f);
                    ushort2 hv = { h_rn(x0), h_rn(x1) };
                    *(ushort2*)&stH[rl * EPIPITCH + cl] = hv;
                }
            }
        }
        __syncthreads();
        #pragma unroll
        for (int i = 0; i < 16; i++) {
            int idx = tid + i * 256;
            int row = idx >> 5, ch = idx & 31;
            uint4 vh = *(uint4*)&stH[row * EPIPITCH + ch * 8];
            size_t go = (size_t)(rowBase + row) * ldB + nBase + ch * 8;
            *(uint4*)&outH[go] = vh;
        }
    } else {
        #pragma unroll
        for (int mi = 0; mi < 4; mi++) {
            #pragma unroll
            for (int ni = 0; ni < 8; ni++) {
                int r0 = rowBase + warp_m + mi * 16 + (lane >> 2);
                int col = nBase + warp_n + ni * 8 + (lane & 3) * 2;
                #pragma unroll
                for (int h = 0; h < 2; h++) {
                    int row = r0 + h * 8;
                    float x0 = acc[mi][ni][h * 2 + 0];
                    float x1 = acc[mi][ni][h * 2 + 1];
                    size_t go = (size_t)row * ldB + col;
                    float2 res = *(const float2*)&residual[go];
                    float2 y = { x0 + res.x, x1 + res.y };
                    *(float2*)&outF[go] = y;
                }
            }
        }
    }
}

// ---------------- launch -------------------------------------------------------
extern "C" void kernel_launch(void* const* d_in, const int* in_sizes, int n_in,
                              void* d_out, int out_size) {
    const float* hidden = (const float*)d_in[0];
    const float* weight = (const float*)d_in[1];
    const float* root   = (const float*)d_in[2];
    const float* bias   = (const float*)d_in[3];
    const float* wo     = (const float*)d_in[4];
    const float* gamma  = (const float*)d_in[5];
    const float* beta   = (const float*)d_in[6];
    const int*   ei     = (const int*)d_in[7];
    const int*   et     = (const int*)d_in[8];
    float* out = (float*)d_out;

    __half *gAhi, *gBhi, *gWhi, *gMhi;
    cudaGetSymbolAddress((void**)&gAhi, g_Ahi);
    cudaGetSymbolAddress((void**)&gBhi, g_Bhi);
    cudaGetSymbolAddress((void**)&gWhi, g_Whi);
    cudaGetSymbolAddress((void**)&gMhi, g_Mhi);

    cudaFuncSetAttribute(gemm_mma, cudaFuncAttributeMaxDynamicSharedMemorySize, SMEM_DYN);

    static cudaStream_t sA = nullptr;
    static cudaEvent_t evFork = nullptr, evA = nullptr;
    if (!sA) {
        cudaStreamCreateWithFlags(&sA, cudaStreamNonBlocking);
        cudaEventCreateWithFlags(&evFork, cudaEventDisableTiming);
        cudaEventCreateWithFlags(&evA,    cudaEventDisableTiming);
    }

    cudaEventRecord(evFork, 0);
    cudaStreamWaitEvent(sA, evFork, 0);

    // stream A: zero -> count -> scan -> bucket
    zero_cnt_kernel<<<NKEY / 256, 256, 0, sA>>>();
    count_kernel<<<NEDGE / 256, 256, 0, sA>>>(ei, et);
    scan_kernel<<<1, 1024, 0, sA>>>();
    bucket_kernel<<<NEDGE / 256, 256, 0, sA>>>(ei, et);
    cudaEventRecord(evA, sA);

    // stream 0: ln + weight converts
    ln_kernel<<<N_NODES, 256>>>(hidden, gamma, beta);
    cvt_kernel<<<2048, 256>>>(weight, gBhi, (size_t)2048 * FINT / 4);
    cvt_kernel<<<1024, 256>>>(root, gBhi + (size_t)2048 * FINT, (size_t)1024 * FINT / 4);
    cvt_kernel<<<1024, 256>>>(wo, gWhi, (size_t)FINT * DMODEL / 4);

    cudaStreamWaitEvent(0, evA, 0);
    gather_kernel<<<NKEY, 128>>>();

    // GEMM1: mid = relu(A[8192,3072] @ [weight;root][3072,4096] + bias) -> fp16
    gemm_mma<<<dim3(FINT / 256, N_NODES / 128), 256, SMEM_DYN>>>(
        gAhi, KTOT, KTOT,
        gBhi, FINT,
        bias, nullptr,
        nullptr, gMhi, 1);

    // GEMM2: out = mid[8192,4096] @ wo[4096,1024] + hidden -> fp32
    gemm_mma<<<dim3(DMODEL / 256, N_NODES / 128), 256, SMEM_DYN>>>(
        gMhi, FINT, FINT,
        gWhi, DMODEL,
        nullptr, hidden,
        out, nullptr, 2);
}

// round 12
// speedup vs baseline: 2.6609x; 1.0217x over previous
#include <cuda_runtime.h>
#include <cuda_fp16.h>
#include <cstdint>
#include <math.h>

#define N_NODES 8192
#define DMODEL 1024
#define FINT 4096
#define KTOT 3072
#define NEDGE 262144
#define NKEY (2 * N_NODES)
#define LN_EPS 1e-6f
#define NROWBLK 64
#define G1_BLOCKS 1024
#define G2_BLOCKS 256

// ---------------- PTX helpers ---------------------------------------------------
__device__ __forceinline__ uint32_t smem_u32(const void* p) {
    uint32_t a;
    asm("{ .reg .u64 t; cvta.to.shared.u64 t, %1; cvt.u32.u64 %0, t; }" : "=r"(a) : "l"(p));
    return a;
}
#define CP16(dst, src) asm volatile("cp.async.cg.shared.global [%0], [%1], 16;" :: "r"(dst), "l"(src))
#define CP_COMMIT()    asm volatile("cp.async.commit_group;" ::: "memory")
#define CP_WAIT2()     asm volatile("cp.async.wait_group 2;" ::: "memory")

__device__ __forceinline__ void ldsm4(uint32_t* r, uint32_t a) {
    asm volatile("ldmatrix.sync.aligned.m8n8.x4.shared.b16 {%0,%1,%2,%3}, [%4];"
                 : "=r"(r[0]), "=r"(r[1]), "=r"(r[2]), "=r"(r[3]) : "r"(a));
}
__device__ __forceinline__ void ldsm4t(uint32_t* r, uint32_t a) {
    asm volatile("ldmatrix.sync.aligned.m8n8.x4.trans.shared.b16 {%0,%1,%2,%3}, [%4];"
                 : "=r"(r[0]), "=r"(r[1]), "=r"(r[2]), "=r"(r[3]) : "r"(a));
}
__device__ __forceinline__ void mma16816(float* d, const uint32_t* a, const uint32_t* b) {
    asm volatile("mma.sync.aligned.m16n8k16.row.col.f32.f16.f16.f32 "
                 "{%0,%1,%2,%3}, {%4,%5,%6,%7}, {%8,%9}, {%0,%1,%2,%3};"
                 : "+f"(d[0]), "+f"(d[1]), "+f"(d[2]), "+f"(d[3])
                 : "r"(a[0]), "r"(a[1]), "r"(a[2]), "r"(a[3]), "r"(b[0]), "r"(b[1]));
}

// ---------------- scratch ----------------------------------------------------
__device__ __half g_xh[(size_t)N_NODES * DMODEL];
__device__ __half g_Ahi[(size_t)N_NODES * KTOT];
__device__ __half g_Bhi[(size_t)KTOT * FINT];
__device__ __half g_Whi[(size_t)FINT * DMODEL];
__device__ __half g_Mhi[(size_t)N_NODES * FINT];
__device__ int g_cnt[NKEY];
__device__ int g_off[NKEY];
__device__ int g_cur[NKEY];
__device__ int g_srcbuf[NEDGE];
__device__ int g_rowdone[NROWBLK];

__device__ __forceinline__ unsigned short h_rn(float x) {
    __half h = __float2half_rn(x);
    return *(unsigned short*)&h;
}

// ---------------- pipeline kernels ---------------------------------------------
__global__ void zero_cnt_kernel() {
    int i = blockIdx.x * blockDim.x + threadIdx.x;
    if (i < NKEY) g_cnt[i] = 0;
    if (i < NROWBLK) g_rowdone[i] = 0;
}

__global__ __launch_bounds__(256) void ln_kernel(const float* __restrict__ hs,
                                                 const float* __restrict__ gamma,
                                                 const float* __restrict__ beta) {
    int n = blockIdx.x;
    int t = threadIdx.x;
    const float4 v = ((const float4*)(hs + (size_t)n * DMODEL))[t];
    float s  = v.x + v.y + v.z + v.w;
    float sq = v.x * v.x + v.y * v.y + v.z * v.z + v.w * v.w;
    __shared__ float red[16];
    for (int o = 16; o > 0; o >>= 1) {
        s  += __shfl_down_sync(0xffffffff, s,  o);
        sq += __shfl_down_sync(0xffffffff, sq, o);
    }
    int wid = t >> 5, lid = t & 31;
    if (lid == 0) { red[wid] = s; red[8 + wid] = sq; }
    __syncthreads();
    if (wid == 0) {
        s  = (lid < 8) ? red[lid]     : 0.f;
        sq = (lid < 8) ? red[8 + lid] : 0.f;
        for (int o = 4; o > 0; o >>= 1) {
            s  += __shfl_down_sync(0xffffffff, s,  o);
            sq += __shfl_down_sync(0xffffffff, sq, o);
        }
        if (lid == 0) { red[0] = s; red[1] = sq; }
    }
    __syncthreads();
    float mean = red[0] * (1.f / DMODEL);
    float var  = red[1] * (1.f / DMODEL) - mean * mean;
    float rstd = rsqrtf(var + LN_EPS);
    const float4 g = ((const float4*)gamma)[t];
    const float4 b = ((const float4*)beta)[t];
    float4 o;
    o.x = (v.x - mean) * rstd * g.x + b.x;
    o.y = (v.y - mean) * rstd * g.y + b.y;
    o.z = (v.z - mean) * rstd * g.z + b.z;
    o.w = (v.w - mean) * rstd * g.w + b.w;
    ushort4 hv = { h_rn(o.x), h_rn(o.y), h_rn(o.z), h_rn(o.w) };
    ((ushort4*)g_xh)[(size_t)n * (DMODEL / 4) + t] = hv;
    size_t a = ((size_t)n * KTOT + 2048) / 4 + t;
    ((ushort4*)g_Ahi)[a] = hv;
}

__global__ void count_kernel(const int* __restrict__ ei, const int* __restrict__ et) {
    int e = blockIdx.x * blockDim.x + threadIdx.x;
    if (e < NEDGE) atomicAdd(&g_cnt[et[e] * N_NODES + ei[NEDGE + e]], 1);
}

__global__ __launch_bounds__(1024) void scan_kernel() {
    int tid = threadIdx.x;
    int lane = tid & 31, wid = tid >> 5;
    int base = tid * 16;
    int loc[16];
    int s = 0;
    #pragma unroll
    for (int i = 0; i < 16; i++) { loc[i] = s; s += g_cnt[base + i]; }
    int inc = s;
    #pragma unroll
    for (int o = 1; o < 32; o <<= 1) {
        int v = __shfl_up_sync(0xffffffff, inc, o);
        if (lane >= o) inc += v;
    }
    __shared__ int wtot[32];
    if (lane == 31) wtot[wid] = inc;
    __syncthreads();
    if (wid == 0) {
        int w = wtot[lane];
        int wi = w;
        #pragma unroll
        for (int o = 1; o < 32; o <<= 1) {
            int v = __shfl_up_sync(0xffffffff, wi, o);
            if (lane >= o) wi += v;
        }
        wtot[lane] = wi - w;
    }
    __syncthreads();
    int ex = wtot[wid] + (inc - s);
    #pragma unroll
    for (int i = 0; i < 16; i++) {
        int o = ex + loc[i];
        g_off[base + i] = o;
        g_cur[base + i] = o;
    }
}

__global__ void bucket_kernel(const int* __restrict__ ei, const int* __restrict__ et) {
    int e = blockIdx.x * blockDim.x + threadIdx.x;
    if (e < NEDGE) {
        int key = et[e] * N_NODES + ei[NEDGE + e];
        int pos = atomicAdd(&g_cur[key], 1);
        g_srcbuf[pos] = ei[e];
    }
}

__global__ __launch_bounds__(128) void gather_kernel() {
    int key = blockIdx.x;
    int node = key & (N_NODES - 1);
    int r = key >> 13;
    int off = g_off[key];
    int cnt = g_cnt[key];
    int t = threadIdx.x;

    float2 acc[4] = { {0.f,0.f}, {0.f,0.f}, {0.f,0.f}, {0.f,0.f} };
    const uint4* xrow = (const uint4*)g_xh;
    int i = 0;
    for (; i + 2 <= cnt; i += 2) {
        int s0 = g_srcbuf[off + i];
        int s1 = g_srcbuf[off + i + 1];
        uint4 v0 = xrow[(size_t)s0 * 128 + t];
        uint4 v1 = xrow[(size_t)s1 * 128 + t];
        const __half2* h0 = (const __half2*)&v0;
        const __half2* h1 = (const __half2*)&v1;
        #pragma unroll
        for (int j = 0; j < 4; j++) {
            float2 f0 = __half22float2(h0[j]);
            float2 f1 = __half22float2(h1[j]);
            acc[j].x += f0.x + f1.x;
            acc[j].y += f0.y + f1.y;
        }
    }
    if (i < cnt) {
        int s0 = g_srcbuf[off + i];
        uint4 v0 = xrow[(size_t)s0 * 128 + t];
        const __half2* h0 = (const __half2*)&v0;
        #pragma unroll
        for (int j = 0; j < 4; j++) {
            float2 f0 = __half22float2(h0[j]);
            acc[j].x += f0.x;
            acc[j].y += f0.y;
        }
    }
    float sc = 1.f / (float)max(cnt, 1);
    ushort4 o0, o1;
    o0.x = h_rn(acc[0].x * sc); o0.y = h_rn(acc[0].y * sc);
    o0.z = h_rn(acc[1].x * sc); o0.w = h_rn(acc[1].y * sc);
    o1.x = h_rn(acc[2].x * sc); o1.y = h_rn(acc[2].y * sc);
    o1.z = h_rn(acc[3].x * sc); o1.w = h_rn(acc[3].y * sc);
    size_t a = ((size_t)node * KTOT + (size_t)r * 1024 + t * 8) >> 2;
    ((ushort4*)g_Ahi)[a] = o0;
    ((ushort4*)g_Ahi)[a + 1] = o1;
}

__global__ void cvt_kernel(const float* __restrict__ src,
                           __half* __restrict__ dst, size_t n4) {
    size_t i = (size_t)blockIdx.x * blockDim.x + threadIdx.x;
    for (; i < n4; i += (size_t)gridDim.x * blockDim.x) {
        float4 v = ((const float4*)src)[i];
        ushort4 hv = { h_rn(v.x), h_rn(v.y), h_rn(v.z), h_rn(v.w) };
        ((ushort4*)dst)[i] = hv;
    }
}

// ---- fused fp16 GEMM1+GEMM2, 1280 blocks --------------------------------------
// blocks [0,1024):  GEMM1 tile (128x256) of mid = relu(A@B + bias)  -> fp16, then
//                   signal rowdone[row].
// blocks [1024,1280): GEMM2 tile (128x256) of out = mid@wo + hidden -> fp32,
//                   after spinning on rowdone[row]==16.
#define STAGE_BYTES 49152
#define OFF_BHI 16384
#define NSTAGE 3
#define SMEM_DYN (NSTAGE * STAGE_BYTES)
#define EPIPITCH 264

__device__ __forceinline__ uint32_t a_off(int row, int q) {
    return (uint32_t)(row * 128 + ((q ^ (row & 7)) << 4));
}
__device__ __forceinline__ uint32_t b_off(int row, int q) {
    return (uint32_t)(row * 512 + (((q & 24) | ((q & 7) ^ (row & 7))) << 4));
}

__global__ __launch_bounds__(256, 1) void gemm_fused(
    const __half* __restrict__ A1, const __half* __restrict__ B1,   // GEMM1 inputs
    const __half* __restrict__ B2,                                   // wo fp16
    __half* __restrict__ mid,                                        // GEMM1 out / GEMM2 in
    const float* __restrict__ bias, const float* __restrict__ residual,
    float* __restrict__ outF)
{
    extern __shared__ __align__(1024) char smem[];
    const uint32_t sb = smem_u32(smem);
    const int tid = threadIdx.x, wid = tid >> 5, lane = tid & 31;
    const int b = blockIdx.x;
    const bool isG1 = (b < G1_BLOCKS);

    int rowBase, nBase, K, ldA, ldB;
    const __half* A;
    const __half* B;
    if (isG1) {
        rowBase = (b >> 4) * 128;
        nBase   = (b & 15) * 256;
        K = KTOT; ldA = KTOT; ldB = FINT;
        A = A1; B = B1;
    } else {
        int j = b - G1_BLOCKS;
        rowBase = (j >> 2) * 128;
        nBase   = (j & 3) * 256;
        K = FINT; ldA = FINT; ldB = DMODEL;
        A = mid; B = B2;
        // wait for GEMM1 to finish this row block
        if (tid == 0) {
            while (atomicAdd(&g_rowdone[rowBase >> 7], 0) < 16) { }
        }
        __syncthreads();
        __threadfence();
    }

    const int warp_m = (wid >> 2) * 64;
    const int warp_n = (wid & 3) * 64;
    const int lr = lane & 15, lc = lane >> 4;
    const int nchunk = K >> 6;

    float acc[4][8][4];
    #pragma unroll
    for (int i = 0; i < 4; i++)
        #pragma unroll
        for (int j = 0; j < 8; j++)
            #pragma unroll
            for (int k = 0; k < 4; k++) acc[i][j][k] = 0.f;

    auto load_chunk = [&](int c, int s) {
        const uint32_t sbase = sb + s * STAGE_BYTES;
        const int kb = c * 64;
        #pragma unroll
        for (int i = 0; i < 4; i++) {
            int v = tid + i * 256;
            int row = v >> 3, q = v & 7;
            uint32_t so = sbase + a_off(row, q);
            size_t g = (size_t)(rowBase + row) * ldA + kb + q * 8;
            CP16(so, A + g);
        }
        #pragma unroll
        for (int i = 0; i < 8; i++) {
            int v = tid + i * 256;
            int row = v >> 5, q = v & 31;
            uint32_t so = sbase + OFF_BHI + b_off(row, q);
            size_t g = (size_t)(kb + row) * ldB + nBase + q * 8;
            CP16(so, B + g);
        }
    };

    load_chunk(0, 0); CP_COMMIT();
    load_chunk(1, 1); CP_COMMIT();
    load_chunk(2, 2); CP_COMMIT();

    for (int c = 0; c < nchunk; c++) {
        CP_WAIT2();
        __syncthreads();
        const int slot = c % NSTAGE;
        const uint32_t base = sb + slot * STAGE_BYTES;
        #pragma unroll
        for (int ks = 0; ks < 4; ks++) {
            uint32_t ah[4][4];
            #pragma unroll
            for (int mi = 0; mi < 4; mi++) {
                int row = warp_m + mi * 16 + lr;
                int q = ks * 2 + lc;
                ldsm4(ah[mi], base + a_off(row, q));
            }
            #pragma unroll
            for (int np = 0; np < 4; np++) {
                int row = ks * 16 + lr;
                int q = (warp_n >> 3) + np * 2 + lc;
                uint32_t th[4];
                ldsm4t(th, base + OFF_BHI + b_off(row, q));
                uint32_t b0[2] = { th[0], th[1] }, b1[2] = { th[2], th[3] };
                #pragma unroll
                for (int mi = 0; mi < 4; mi++) {
                    mma16816(acc[mi][np * 2], ah[mi], b0);
                    mma16816(acc[mi][np * 2 + 1], ah[mi], b1);
                }
            }
        }
        __syncthreads();
        if (c + NSTAGE < nchunk) load_chunk(c + NSTAGE, slot);
        CP_COMMIT();
    }

    if (isG1) {
        unsigned short* stH = (unsigned short*)smem;
        #pragma unroll
        for (int mi = 0; mi < 4; mi++) {
            #pragma unroll
            for (int ni = 0; ni < 8; ni++) {
                int rl0 = warp_m + mi * 16 + (lane >> 2);
                int cl  = warp_n + ni * 8 + (lane & 3) * 2;
                #pragma unroll
                for (int h = 0; h < 2; h++) {
                    int rl = rl0 + h * 8;
                    float x0 = acc[mi][ni][h * 2 + 0];
                    float x1 = acc[mi][ni][h * 2 + 1];
                    int gc = nBase + cl;
                    x0 = fmaxf(x0 + bias[gc], 0.f);
                    x1 = fmaxf(x1 + bias[gc + 1], 0.f);
                    ushort2 hv = { h_rn(x0), h_rn(x1) };
                    *(ushort2*)&stH[rl * EPIPITCH + cl] = hv;
                }
            }
        }
        __syncthreads();
        #pragma unroll
        for (int i = 0; i < 16; i++) {
            int idx = tid + i * 256;
            int row = idx >> 5, ch = idx & 31;
            uint4 vh = *(uint4*)&stH[row * EPIPITCH + ch * 8];
            size_t go = (size_t)(rowBase + row) * ldB + nBase + ch * 8;
            *(uint4*)&mid[go] = vh;
        }
        // signal: this row block's column tile is complete
        __threadfence();
        __syncthreads();
        if (tid == 0) atomicAdd(&g_rowdone[rowBase >> 7], 1);
    } else {
        #pragma unroll
        for (int mi = 0; mi < 4; mi++) {
            #pragma unroll
            for (int ni = 0; ni < 8; ni++) {
                int r0 = rowBase + warp_m + mi * 16 + (lane >> 2);
                int col = nBase + warp_n + ni * 8 + (lane & 3) * 2;
                #pragma unroll
                for (int h = 0; h < 2; h++) {
                    int row = r0 + h * 8;
                    float x0 = acc[mi][ni][h * 2 + 0];
                    float x1 = acc[mi][ni][h * 2 + 1];
                    size_t go = (size_t)row * ldB + col;
                    float2 res = *(const float2*)&residual[go];
                    float2 y = { x0 + res.x, x1 + res.y };
                    *(float2*)&outF[go] = y;
                }
            }
        }
    }
}

// ---------------- launch -------------------------------------------------------
extern "C" void kernel_launch(void* const* d_in, const int* in_sizes, int n_in,
                              void* d_out, int out_size) {
    const float* hidden = (const float*)d_in[0];
    const float* weight = (const float*)d_in[1];
    const float* root   = (const float*)d_in[2];
    const float* bias   = (const float*)d_in[3];
    const float* wo     = (const float*)d_in[4];
    const float* gamma  = (const float*)d_in[5];
    const float* beta   = (const float*)d_in[6];
    const int*   ei     = (const int*)d_in[7];
    const int*   et     = (const int*)d_in[8];
    float* out = (float*)d_out;

    __half *gAhi, *gBhi, *gWhi, *gMhi;
    cudaGetSymbolAddress((void**)&gAhi, g_Ahi);
    cudaGetSymbolAddress((void**)&gBhi, g_Bhi);
    cudaGetSymbolAddress((void**)&gWhi, g_Whi);
    cudaGetSymbolAddress((void**)&gMhi, g_Mhi);

    cudaFuncSetAttribute(gemm_fused, cudaFuncAttributeMaxDynamicSharedMemorySize, SMEM_DYN);

    static cudaStream_t sA = nullptr;
    static cudaEvent_t evFork = nullptr, evA = nullptr;
    if (!sA) {
        cudaStreamCreateWithFlags(&sA, cudaStreamNonBlocking);
        cudaEventCreateWithFlags(&evFork, cudaEventDisableTiming);
        cudaEventCreateWithFlags(&evA,    cudaEventDisableTiming);
    }

    cudaEventRecord(evFork, 0);
    cudaStreamWaitEvent(sA, evFork, 0);

    // stream A: zero -> count -> scan -> bucket
    zero_cnt_kernel<<<NKEY / 256, 256, 0, sA>>>();
    count_kernel<<<NEDGE / 256, 256, 0, sA>>>(ei, et);
    scan_kernel<<<1, 1024, 0, sA>>>();
    bucket_kernel<<<NEDGE / 256, 256, 0, sA>>>(ei, et);
    cudaEventRecord(evA, sA);

    // stream 0: ln + weight converts
    ln_kernel<<<N_NODES, 256>>>(hidden, gamma, beta);
    cvt_kernel<<<2048, 256>>>(weight, gBhi, (size_t)2048 * FINT / 4);
    cvt_kernel<<<1024, 256>>>(root, gBhi + (size_t)2048 * FINT, (size_t)1024 * FINT / 4);
    cvt_kernel<<<1024, 256>>>(wo, gWhi, (size_t)FINT * DMODEL / 4);

    cudaStreamWaitEvent(0, evA, 0);
    gather_kernel<<<NKEY, 128>>>();

    // fused GEMM1 + GEMM2 (flag-based row dependency)
    gemm_fused<<<G1_BLOCKS + G2_BLOCKS, 256, SMEM_DYN>>>(
        gAhi, gBhi, gWhi, gMhi, bias, hidden, out);
}